// round 12
// baseline (speedup 1.0000x reference)
#include <cuda_runtime.h>
#include <cuda_bf16.h>
#include <cstdint>

// Problem constants: B=8, H=W=64, N=4096, C=256, nh=8, nh2=4, hd=32, sr=8
#define BATCH 8
#define NTOK 4096
#define CH 256

// ---------------------------------------------------------------------------
// Scratch (device globals) — hi/lo bf16 PLANES (deinterleaved)
// ---------------------------------------------------------------------------
__device__ __nv_bfloat16 g_xhi [(size_t)BATCH * NTOK * CH], g_xlo [(size_t)BATCH * NTOK * CH];
__device__ __nv_bfloat16 g_qhi [(size_t)BATCH * NTOK * CH], g_qlo [(size_t)BATCH * NTOK * CH];
__device__ __nv_bfloat16 g_cathi[(size_t)BATCH * NTOK * CH], g_catlo[(size_t)BATCH * NTOK * CH];
__device__ __nv_bfloat16 g_x1hi[BATCH * 256 * CH], g_x1lo[BATCH * 256 * CH];
__device__ __nv_bfloat16 g_x2hi[BATCH * 64 * CH],  g_x2lo[BATCH * 64 * CH];
__device__ float         g_kv1 [BATCH * 256 * CH];
__device__ float         g_kv2 [BATCH * 64 * CH];
__device__ __nv_bfloat16 g_k1hi[BATCH * 256 * 128], g_k1lo[BATCH * 256 * 128];
__device__ __nv_bfloat16 g_k2hi[BATCH * 64 * 128],  g_k2lo[BATCH * 64 * 128];
__device__ __nv_bfloat16 g_v1hi[BATCH * 4 * 32 * 256], g_v1lo[BATCH * 4 * 32 * 256];
__device__ __nv_bfloat16 g_v2hi[BATCH * 4 * 32 * 64],  g_v2lo[BATCH * 4 * 32 * 64];
// weight splits (already planes)
__device__ __nv_bfloat16 g_qwh [256 * 256], g_qwl [256 * 256];
__device__ __nv_bfloat16 g_k1wh[256 * 256], g_k1wl[256 * 256];
__device__ __nv_bfloat16 g_k2wh[256 * 256], g_k2wl[256 * 256];
__device__ __nv_bfloat16 g_pwh [256 * 256], g_pwl [256 * 256];

// ---------------------------------------------------------------------------
// helpers
// ---------------------------------------------------------------------------
__device__ __forceinline__ void split_bf(float v, __nv_bfloat16& h, __nv_bfloat16& l) {
    h = __float2bfloat16(v);
    l = __float2bfloat16(v - __bfloat162float(h));
}

// Two fp32 -> bf16x2 hi-pair + residual lo-pair (elem0 in low half).
__device__ __forceinline__ void pack2_hilo(
    float p0, float p1, uint32_t& h, uint32_t& l)
{
    uint32_t hp;
    asm("cvt.rn.bf16x2.f32 %0, %1, %2;" : "=r"(hp) : "f"(p1), "f"(p0));
    const float r0 = p0 - __uint_as_float(hp << 16);
    const float r1 = p1 - __uint_as_float(hp & 0xffff0000u);
    uint32_t lp;
    asm("cvt.rn.bf16x2.f32 %0, %1, %2;" : "=r"(lp) : "f"(r1), "f"(r0));
    h = hp; l = lp;
}

__device__ __forceinline__ void mma16816(
    float* c, const uint32_t* a, const uint32_t* b)
{
    asm volatile(
        "mma.sync.aligned.m16n8k16.row.col.f32.bf16.bf16.f32 "
        "{%0,%1,%2,%3}, {%4,%5,%6,%7}, {%8,%9}, {%0,%1,%2,%3};"
        : "+f"(c[0]), "+f"(c[1]), "+f"(c[2]), "+f"(c[3])
        : "r"(a[0]), "r"(a[1]), "r"(a[2]), "r"(a[3]), "r"(b[0]), "r"(b[1]));
}

__device__ __forceinline__ void cpa16(void* dst, const void* src) {
    uint32_t d = (uint32_t)__cvta_generic_to_shared(dst);
    asm volatile("cp.async.cg.shared.global [%0], [%1], 16;\n"
                 :: "r"(d), "l"(src));
}

// ---------------------------------------------------------------------------
// GEMM body v1 (round-9 structure) with DEINTERLEAVED A planes.
// 512 threads, 128x256 tile, 3-stage cp.async. 16 warps = 4m x 4n.
// MODE 0: fp32 out (+bias). MODE 1: q planes out. MODE 2: fp32 + k planes.
// ---------------------------------------------------------------------------
template<int MODE>
__device__ __forceinline__ void gemm_body(
    const __nv_bfloat16* __restrict__ Ahi,
    const __nv_bfloat16* __restrict__ Alo,
    const __nv_bfloat16* __restrict__ Wh,
    const __nv_bfloat16* __restrict__ Wl,
    const float* __restrict__ bias,
    float* __restrict__ Cf,
    __nv_bfloat16* __restrict__ Chi, __nv_bfloat16* __restrict__ Clo,
    int m0, char* smraw)
{
    constexpr int LD  = 40;            // bf16 per row (32 data + 8 pad)
    constexpr int ASZ = 128 * LD;      // elems per A plane stage
    constexpr int BSZ = 256 * LD;

    __nv_bfloat16* Ah = (__nv_bfloat16*)smraw;   // [3][128][LD]
    __nv_bfloat16* Al = Ah + 3 * ASZ;
    __nv_bfloat16* Bh = Al + 3 * ASZ;            // [3][256][LD]
    __nv_bfloat16* Bl = Bh + 3 * BSZ;

    const int tid = threadIdx.x;
    const int w = tid >> 5, lane = tid & 31;
    const int wm = w & 3, wn = w >> 2;
    const int g = lane >> 2, qk = (lane & 3) * 2;

    auto load_stage = [&](int s, int k0) {
        {   // Ahi, Alo: 512 chunks each, 1 per thread
            const int row = tid >> 2, ch = tid & 3;
            cpa16(&Ah[s * ASZ + row * LD + ch * 8],
                  &Ahi[(size_t)(m0 + row) * 256 + k0 + ch * 8]);
            cpa16(&Al[s * ASZ + row * LD + ch * 8],
                  &Alo[(size_t)(m0 + row) * 256 + k0 + ch * 8]);
        }
#pragma unroll
        for (int i = 0; i < 2; i++) {
            const int c = tid + i * 512;
            const int row = c >> 2, ch = c & 3;
            cpa16(&Bh[s * BSZ + row * LD + ch * 8],
                  &Wh[(size_t)row * 256 + k0 + ch * 8]);
        }
#pragma unroll
        for (int i = 0; i < 2; i++) {
            const int c = tid + i * 512;
            const int row = c >> 2, ch = c & 3;
            cpa16(&Bl[s * BSZ + row * LD + ch * 8],
                  &Wl[(size_t)row * 256 + k0 + ch * 8]);
        }
        asm volatile("cp.async.commit_group;\n" ::: "memory");
    };

    float acc[2][8][4];
#pragma unroll
    for (int mt = 0; mt < 2; mt++)
#pragma unroll
        for (int nt = 0; nt < 8; nt++)
#pragma unroll
            for (int r = 0; r < 4; r++) acc[mt][nt][r] = 0.f;

    load_stage(0, 0);
    load_stage(1, 32);

    for (int it = 0; it < 8; it++) {
        if (it < 7) asm volatile("cp.async.wait_group 1;\n" ::: "memory");
        else        asm volatile("cp.async.wait_group 0;\n" ::: "memory");
        __syncthreads();
        if (it + 2 < 8) load_stage((it + 2) % 3, (it + 2) * 32);

        const int s = it % 3;
        const __nv_bfloat16* Ahs = Ah + s * ASZ;
        const __nv_bfloat16* Als = Al + s * ASZ;
        const __nv_bfloat16* Bhs = Bh + s * BSZ;
        const __nv_bfloat16* Bls = Bl + s * BSZ;

#pragma unroll
        for (int ks = 0; ks < 2; ks++) {
            const int kb = ks * 16;
            uint32_t ah[2][4], al[2][4];
#pragma unroll
            for (int mt = 0; mt < 2; mt++) {
                const int row = wm * 32 + mt * 16 + g;
                const int o0 = row * LD + kb + qk;
                ah[mt][0] = *(const uint32_t*)&Ahs[o0];
                ah[mt][1] = *(const uint32_t*)&Ahs[o0 + 8 * LD];
                ah[mt][2] = *(const uint32_t*)&Ahs[o0 + 8];
                ah[mt][3] = *(const uint32_t*)&Ahs[o0 + 8 * LD + 8];
                al[mt][0] = *(const uint32_t*)&Als[o0];
                al[mt][1] = *(const uint32_t*)&Als[o0 + 8 * LD];
                al[mt][2] = *(const uint32_t*)&Als[o0 + 8];
                al[mt][3] = *(const uint32_t*)&Als[o0 + 8 * LD + 8];
            }
            uint32_t bf[8][2];
#pragma unroll
            for (int nt = 0; nt < 8; nt++) {
                const __nv_bfloat16* pb = &Bhs[(wn * 64 + nt * 8 + g) * LD + kb + qk];
                bf[nt][0] = *(const uint32_t*)pb;
                bf[nt][1] = *(const uint32_t*)(pb + 8);
            }
#pragma unroll
            for (int mt = 0; mt < 2; mt++)
#pragma unroll
                for (int nt = 0; nt < 8; nt++) {
                    mma16816(acc[mt][nt], ah[mt], bf[nt]);
                    mma16816(acc[mt][nt], al[mt], bf[nt]);
                }
#pragma unroll
            for (int nt = 0; nt < 8; nt++) {
                const __nv_bfloat16* pb = &Bls[(wn * 64 + nt * 8 + g) * LD + kb + qk];
                bf[nt][0] = *(const uint32_t*)pb;
                bf[nt][1] = *(const uint32_t*)(pb + 8);
            }
#pragma unroll
            for (int mt = 0; mt < 2; mt++)
#pragma unroll
                for (int nt = 0; nt < 8; nt++)
                    mma16816(acc[mt][nt], ah[mt], bf[nt]);
        }
        __syncthreads();
    }

#pragma unroll
    for (int mt = 0; mt < 2; mt++) {
        const int r = m0 + wm * 32 + mt * 16 + g;
#pragma unroll
        for (int nt = 0; nt < 8; nt++) {
            const int col = wn * 64 + nt * 8 + qk;
            if constexpr (MODE == 0) {
                const float b0 = bias[col], b1 = bias[col + 1];
                *(float2*)&Cf[(size_t)r * 256 + col] =
                    make_float2(acc[mt][nt][0] + b0, acc[mt][nt][1] + b1);
                *(float2*)&Cf[(size_t)(r + 8) * 256 + col] =
                    make_float2(acc[mt][nt][2] + b0, acc[mt][nt][3] + b1);
            } else if constexpr (MODE == 1) {
                uint32_t hp, lp;
                pack2_hilo(acc[mt][nt][0], acc[mt][nt][1], hp, lp);
                *(uint32_t*)&Chi[(size_t)r * 256 + col] = hp;
                *(uint32_t*)&Clo[(size_t)r * 256 + col] = lp;
                pack2_hilo(acc[mt][nt][2], acc[mt][nt][3], hp, lp);
                *(uint32_t*)&Chi[(size_t)(r + 8) * 256 + col] = hp;
                *(uint32_t*)&Clo[(size_t)(r + 8) * 256 + col] = lp;
            } else {
                *(float2*)&Cf[(size_t)r * 256 + col] =
                    make_float2(acc[mt][nt][0], acc[mt][nt][1]);
                *(float2*)&Cf[(size_t)(r + 8) * 256 + col] =
                    make_float2(acc[mt][nt][2], acc[mt][nt][3]);
                if (col < 128) {
                    uint32_t hp, lp;
                    pack2_hilo(acc[mt][nt][0], acc[mt][nt][1], hp, lp);
                    *(uint32_t*)&Chi[(size_t)r * 128 + col] = hp;
                    *(uint32_t*)&Clo[(size_t)r * 128 + col] = lp;
                    pack2_hilo(acc[mt][nt][2], acc[mt][nt][3], hp, lp);
                    *(uint32_t*)&Chi[(size_t)(r + 8) * 128 + col] = hp;
                    *(uint32_t*)&Clo[(size_t)(r + 8) * 128 + col] = lp;
                }
            }
        }
    }
}

// Combined projection GEMMs: q (256 blocks) + kv1 (16) + kv2 (4).
__global__ __launch_bounds__(512) void gemm_all(
    const __nv_bfloat16* __restrict__ xhi, const __nv_bfloat16* __restrict__ xlo,
    const __nv_bfloat16* __restrict__ x1hi, const __nv_bfloat16* __restrict__ x1lo,
    const __nv_bfloat16* __restrict__ x2hi, const __nv_bfloat16* __restrict__ x2lo,
    const __nv_bfloat16* __restrict__ qwh, const __nv_bfloat16* __restrict__ qwl,
    const __nv_bfloat16* __restrict__ k1wh, const __nv_bfloat16* __restrict__ k1wl,
    const __nv_bfloat16* __restrict__ k2wh, const __nv_bfloat16* __restrict__ k2wl,
    __nv_bfloat16* __restrict__ qhi, __nv_bfloat16* __restrict__ qlo,
    float* __restrict__ kv1,
    __nv_bfloat16* __restrict__ k1hi, __nv_bfloat16* __restrict__ k1lo,
    float* __restrict__ kv2,
    __nv_bfloat16* __restrict__ k2hi, __nv_bfloat16* __restrict__ k2lo)
{
    extern __shared__ __align__(16) char smraw[];
    if (blockIdx.x < 256)
        gemm_body<1>(xhi, xlo, qwh, qwl, nullptr, nullptr, qhi, qlo,
                     blockIdx.x * 128, smraw);
    else if (blockIdx.x < 272)
        gemm_body<2>(x1hi, x1lo, k1wh, k1wl, nullptr, kv1, k1hi, k1lo,
                     (blockIdx.x - 256) * 128, smraw);
    else
        gemm_body<2>(x2hi, x2lo, k2wh, k2wl, nullptr, kv2, k2hi, k2lo,
                     (blockIdx.x - 272) * 128, smraw);
}

// Output projection.
__global__ __launch_bounds__(512) void gemm_proj(
    const __nv_bfloat16* __restrict__ Ahi, const __nv_bfloat16* __restrict__ Alo,
    const __nv_bfloat16* __restrict__ Wh, const __nv_bfloat16* __restrict__ Wl,
    const float* __restrict__ bias, float* __restrict__ Cf)
{
    extern __shared__ __align__(16) char smraw[];
    gemm_body<0>(Ahi, Alo, Wh, Wl, bias, Cf, nullptr, nullptr,
                 blockIdx.x * 128, smraw);
}

// ---------------------------------------------------------------------------
// LN + exact GELU block helper (per 256-thread window group)
// ---------------------------------------------------------------------------
__device__ __forceinline__ float ln_gelu_block(
    float a, const float* __restrict__ g, const float* __restrict__ bln,
    float* red, int c)
{
    float s1 = a, s2 = a * a;
#pragma unroll
    for (int o = 16; o > 0; o >>= 1) {
        s1 += __shfl_xor_sync(0xffffffffu, s1, o);
        s2 += __shfl_xor_sync(0xffffffffu, s2, o);
    }
    if ((c & 31) == 0) { red[c >> 5] = s1; red[8 + (c >> 5)] = s2; }
    __syncthreads();
    if (c == 0) {
        float a0 = 0.f, b0 = 0.f;
#pragma unroll
        for (int i = 0; i < 8; i++) { a0 += red[i]; b0 += red[8 + i]; }
        red[0] = a0; red[8] = b0;
    }
    __syncthreads();
    const float mean = red[0] * (1.f / 256.f);
    const float var  = red[8] * (1.f / 256.f) - mean * mean;
    float y = (a - mean) * rsqrtf(var + 1e-5f) * g[c] + bln[c];
    y = 0.5f * y * (1.0f + erff(y * 0.70710678118654752f));
    __syncthreads();
    return y;
}

// ---------------------------------------------------------------------------
// dwconv_fused + x-plane pack + weight split
// ---------------------------------------------------------------------------
__global__ __launch_bounds__(512) void dwconv_wsplit(
    const float* __restrict__ x,
    __nv_bfloat16* __restrict__ xhi, __nv_bfloat16* __restrict__ xlo,
    const float* __restrict__ w1, const float* __restrict__ b1c,
    const float* __restrict__ g1, const float* __restrict__ bl1,
    const float* __restrict__ w2, const float* __restrict__ b2c,
    const float* __restrict__ g2, const float* __restrict__ bl2,
    __nv_bfloat16* __restrict__ x1hi, __nv_bfloat16* __restrict__ x1lo,
    __nv_bfloat16* __restrict__ x2hi, __nv_bfloat16* __restrict__ x2lo,
    const float* __restrict__ w0m, const float* __restrict__ w1m,
    const float* __restrict__ w2m, const float* __restrict__ w3m,
    __nv_bfloat16* __restrict__ h0, __nv_bfloat16* __restrict__ l0,
    __nv_bfloat16* __restrict__ h1, __nv_bfloat16* __restrict__ l1,
    __nv_bfloat16* __restrict__ h2, __nv_bfloat16* __restrict__ l2,
    __nv_bfloat16* __restrict__ h3, __nv_bfloat16* __restrict__ l3)
{
    if (blockIdx.x >= 256) {
        const int widx = blockIdx.x - 256;
        const int which = widx >> 7;
        const int i = (widx & 127) * 512 + threadIdx.x;
        const float* in = which == 0 ? w0m : which == 1 ? w1m : which == 2 ? w2m : w3m;
        __nv_bfloat16* oh = which == 0 ? h0 : which == 1 ? h1 : which == 2 ? h2 : h3;
        __nv_bfloat16* ol = which == 0 ? l0 : which == 1 ? l1 : which == 2 ? l2 : l3;
        __nv_bfloat16 hh, ll;
        split_bf(in[i], hh, ll);
        oh[i] = hh; ol[i] = ll;
        return;
    }

    extern __shared__ float sw[];
    float* w2s = sw;
    float* w1s = sw + 64 * 257;
    float* redb = sw + 80 * 257;

    const int tid = threadIdx.x;
    const int c = tid & 255;
    const int win = tid >> 8;
    float* red = redb + win * 16;

    const int b = blockIdx.x >> 5;
    const int pair = blockIdx.x & 31;
    const int t2 = pair * 2 + win;
    const int oh2 = t2 >> 3, ow2 = t2 & 7;

    for (int i = tid; i < 64 * 256; i += 512)
        w2s[(i & 63) * 257 + (i >> 6)] = w2[i];
    for (int i = tid; i < 16 * 256; i += 512)
        w1s[(i & 15) * 257 + (i >> 4)] = w1[i];
    __syncthreads();

    float acc2 = b2c[c];
    float acc1[2][2];
    acc1[0][0] = acc1[0][1] = acc1[1][0] = acc1[1][1] = b1c[c];

#pragma unroll
    for (int kh = 0; kh < 8; kh++) {
#pragma unroll
        for (int kw = 0; kw < 8; kw++) {
            const int ih = oh2 * 8 + kh, iw = ow2 * 8 + kw;
            const size_t xi = ((size_t)b * NTOK + ih * 64 + iw) * CH + c;
            const float xv = x[xi];
            __nv_bfloat16 hh, ll;
            split_bf(xv, hh, ll);
            xhi[xi] = hh; xlo[xi] = ll;
            acc2 += xv * w2s[(kh * 8 + kw) * 257 + c];
            acc1[kh >> 2][kw >> 2] += xv * w1s[((kh & 3) * 4 + (kw & 3)) * 257 + c];
        }
    }

    {
        const float y2 = ln_gelu_block(acc2, g2, bl2, red, c);
        __nv_bfloat16 hh, ll;
        split_bf(y2, hh, ll);
        const size_t o = ((size_t)b * 64 + t2) * CH + c;
        x2hi[o] = hh; x2lo[o] = ll;
    }
#pragma unroll
    for (int i = 0; i < 2; i++)
#pragma unroll
        for (int j = 0; j < 2; j++) {
            const float y1 = ln_gelu_block(acc1[i][j], g1, bl1, red, c);
            const int t1 = (oh2 * 2 + i) * 16 + (ow2 * 2 + j);
            __nv_bfloat16 hh, ll;
            split_bf(y1, hh, ll);
            const size_t o = ((size_t)b * 256 + t1) * CH + c;
            x1hi[o] = hh; x1lo[o] = ll;
        }
}

// ---------------------------------------------------------------------------
// Fused v local conv (+residual) -> V^T hi/lo planes [b,h][e][s]
// ---------------------------------------------------------------------------
__global__ __launch_bounds__(128) void vconv_fused(
    const float* __restrict__ kv1, const float* __restrict__ lcw1,
    const float* __restrict__ lcb1,
    __nv_bfloat16* __restrict__ v1hi, __nv_bfloat16* __restrict__ v1lo,
    const float* __restrict__ kv2, const float* __restrict__ lcw2,
    const float* __restrict__ lcb2,
    __nv_bfloat16* __restrict__ v2hi, __nv_bfloat16* __restrict__ v2lo)
{
    int token, HS;
    const float *kv, *lcw, *lcb;
    __nv_bfloat16 *vh, *vl;
    if (blockIdx.x < BATCH * 256) {
        token = blockIdx.x; HS = 16; kv = kv1; lcw = lcw1; lcb = lcb1;
        vh = v1hi; vl = v1lo;
    } else {
        token = blockIdx.x - BATCH * 256; HS = 8; kv = kv2; lcw = lcw2; lcb = lcb2;
        vh = v2hi; vl = v2lo;
    }
    const int NS = HS * HS;
    const int b  = token / NS;
    const int s  = token - b * NS;
    const int hs = s / HS, ws = s - hs * HS;
    const int c  = threadIdx.x;

    float acc = lcb[c];
#pragma unroll
    for (int kh = 0; kh < 3; kh++)
#pragma unroll
        for (int kw = 0; kw < 3; kw++) {
            const int ih = hs - 1 + kh, iw = ws - 1 + kw;
            if (ih >= 0 && ih < HS && iw >= 0 && iw < HS)
                acc += kv[((size_t)b * NS + ih * HS + iw) * 256 + 128 + c]
                     * lcw[c * 9 + kh * 3 + kw];
        }
    const float v = kv[(size_t)token * 256 + 128 + c] + acc;
    const int h = c >> 5, e = c & 31;
    __nv_bfloat16 hh, ll;
    split_bf(v, hh, ll);
    const size_t o = (((size_t)b * 4 + h) * 32 + e) * NS + s;
    vh[o] = hh; vl[o] = ll;
}

// ---------------------------------------------------------------------------
// Flash attention (round-9 structure) with hi/lo PLANES (no byte_perm).
// 64 q / 256 threads / 2 blocks per SM.
// ---------------------------------------------------------------------------
template<int NS>
__device__ __forceinline__ void attn_body(
    const __nv_bfloat16* __restrict__ qhi, const __nv_bfloat16* __restrict__ qlo,
    const __nv_bfloat16* __restrict__ khi, const __nv_bfloat16* __restrict__ klo,
    const __nv_bfloat16* __restrict__ vhi, const __nv_bfloat16* __restrict__ vlo,
    __nv_bfloat16* __restrict__ cathi, __nv_bfloat16* __restrict__ catlo,
    int qoff, int ooff, int bh, char* smc)
{
    constexpr int SCH = NS / 4;
    constexpr int NT2 = SCH / 8;
    constexpr int KT  = SCH / 16;
    constexpr int LD  = 40;            // bf16 row stride (Q/K planes)
    constexpr int VSP = NS + 8;        // bf16 row stride (V planes)
    // smem element offsets (bf16)
    constexpr int QE = 64 * LD;
    constexpr int OFF_QLO = QE;
    constexpr int OFF_KHI = 2 * QE;
    constexpr int KE = NS * LD;
    constexpr int OFF_KLO = OFF_KHI + KE;
    constexpr int OFF_VHI = OFF_KHI + 2 * KE;
    constexpr int VE = 32 * VSP;
    constexpr int OFF_VLO = OFF_VHI + VE;
    constexpr int VEND_B = (OFF_VHI + 2 * VE) * 2;
    constexpr int QKEND_B = (OFF_KHI + 2 * KE) * 2;
    constexpr int PB_B = 8 * 32 * 34 * 4;
    constexpr int OFF_PB_B = (QKEND_B >= PB_B) ? 0 : VEND_B;
    constexpr int PBEND_B = OFF_PB_B + PB_B;
    constexpr int OFF_ST_B = (PBEND_B > VEND_B) ? PBEND_B : VEND_B;
    const float kfac = 0.17677669529663689f * 1.4426950408889634f;

    __nv_bfloat16* Qh = (__nv_bfloat16*)smc;
    __nv_bfloat16* Ql = Qh + OFF_QLO;
    __nv_bfloat16* Kh = Qh + OFF_KHI;
    __nv_bfloat16* Kl = Qh + OFF_KLO;
    __nv_bfloat16* Vh = Qh + OFF_VHI;
    __nv_bfloat16* Vl = Qh + OFF_VLO;
    float* pb  = (float*)(smc + OFF_PB_B);
    float* mx  = (float*)(smc + OFF_ST_B);
    float* smr = mx + 256;

    const int b = bh >> 2, h = bh & 3;
    const int q0 = blockIdx.y * 64;
    const int tid = threadIdx.x, lane = tid & 31, w = tid >> 5;
    const int g = lane >> 2, qk = (lane & 3) * 2;
    const int wm = w >> 2, wn = w & 3;

    // ---- async staging: Q+K (group 0), V (group 1) ----
    {
        const int row = tid >> 2, ch = tid & 3;   // 256 chunks each Q plane
        cpa16(&Qh[row * LD + ch * 8],
              &qhi[((size_t)(b * 4096 + q0 + row)) * 256 + qoff + h * 32 + ch * 8]);
        cpa16(&Ql[row * LD + ch * 8],
              &qlo[((size_t)(b * 4096 + q0 + row)) * 256 + qoff + h * 32 + ch * 8]);
    }
    for (int c = tid; c < NS * 4; c += 256) {
        const int s = c >> 2, ch = c & 3;
        cpa16(&Kh[s * LD + ch * 8],
              &khi[((size_t)(b * NS + s)) * 128 + h * 32 + ch * 8]);
        cpa16(&Kl[s * LD + ch * 8],
              &klo[((size_t)(b * NS + s)) * 128 + h * 32 + ch * 8]);
    }
    asm volatile("cp.async.commit_group;\n" ::: "memory");
    for (int c = tid; c < 32 * (NS / 8); c += 256) {
        const int e = c / (NS / 8), s8 = c % (NS / 8);
        cpa16(&Vh[e * VSP + s8 * 8],
              &vhi[(((size_t)(b * 4 + h)) * 32 + e) * NS + s8 * 8]);
        cpa16(&Vl[e * VSP + s8 * 8],
              &vlo[(((size_t)(b * 4 + h)) * 32 + e) * NS + s8 * 8]);
    }
    asm volatile("cp.async.commit_group;\n" ::: "memory");
    asm volatile("cp.async.wait_group 1;\n" ::: "memory");
    __syncthreads();

    // ---- phase 1: S = Q K^T into registers ----
    float acc[2][NT2][4];
#pragma unroll
    for (int mt = 0; mt < 2; mt++)
#pragma unroll
        for (int nt = 0; nt < NT2; nt++)
#pragma unroll
            for (int r = 0; r < 4; r++) acc[mt][nt][r] = 0.f;

#pragma unroll
    for (int kc = 0; kc < 2; kc++) {
        const int kb = kc * 16;
        uint32_t ah[2][4], al[2][4];
#pragma unroll
        for (int mt = 0; mt < 2; mt++) {
            const int row = wm * 32 + mt * 16 + g;
            const int o0 = row * LD + kb + qk;
            ah[mt][0] = *(const uint32_t*)&Qh[o0];
            ah[mt][1] = *(const uint32_t*)&Qh[o0 + 8 * LD];
            ah[mt][2] = *(const uint32_t*)&Qh[o0 + 8];
            ah[mt][3] = *(const uint32_t*)&Qh[o0 + 8 * LD + 8];
            al[mt][0] = *(const uint32_t*)&Ql[o0];
            al[mt][1] = *(const uint32_t*)&Ql[o0 + 8 * LD];
            al[mt][2] = *(const uint32_t*)&Ql[o0 + 8];
            al[mt][3] = *(const uint32_t*)&Ql[o0 + 8 * LD + 8];
        }
#pragma unroll
        for (int nt = 0; nt < NT2; nt++) {
            const int srow = wn * SCH + nt * 8 + g;
            const int o0 = srow * LD + kb + qk;
            uint32_t bh2[2], bl2[2];
            bh2[0] = *(const uint32_t*)&Kh[o0];
            bh2[1] = *(const uint32_t*)&Kh[o0 + 8];
            bl2[0] = *(const uint32_t*)&Kl[o0];
            bl2[1] = *(const uint32_t*)&Kl[o0 + 8];
#pragma unroll
            for (int mt = 0; mt < 2; mt++) {
                mma16816(acc[mt][nt], ah[mt], bh2);
                mma16816(acc[mt][nt], al[mt], bh2);
                mma16816(acc[mt][nt], ah[mt], bl2);
            }
        }
    }

    // ---- chunk max ----
#pragma unroll
    for (int mt = 0; mt < 2; mt++)
#pragma unroll
        for (int half = 0; half < 2; half++) {
            float m = acc[mt][0][half * 2];
#pragma unroll
            for (int nt = 0; nt < NT2; nt++) {
                m = fmaxf(m, acc[mt][nt][half * 2]);
                m = fmaxf(m, acc[mt][nt][half * 2 + 1]);
            }
            m = fmaxf(m, __shfl_xor_sync(0xffffffffu, m, 1));
            m = fmaxf(m, __shfl_xor_sync(0xffffffffu, m, 2));
            if ((lane & 3) == 0)
                mx[wn * 64 + wm * 32 + mt * 16 + half * 8 + g] = m;
        }
    __syncthreads();   // barrier 1

    // ---- global max, exp, chunk sums ----
#pragma unroll
    for (int mt = 0; mt < 2; mt++)
#pragma unroll
        for (int half = 0; half < 2; half++) {
            const int row = wm * 32 + mt * 16 + half * 8 + g;
            float m = fmaxf(fmaxf(mx[row], mx[64 + row]),
                            fmaxf(mx[128 + row], mx[192 + row]));
            float s = 0.f;
#pragma unroll
            for (int nt = 0; nt < NT2; nt++) {
                float e0 = exp2f((acc[mt][nt][half * 2]     - m) * kfac);
                float e1 = exp2f((acc[mt][nt][half * 2 + 1] - m) * kfac);
                acc[mt][nt][half * 2]     = e0;
                acc[mt][nt][half * 2 + 1] = e1;
                s += e0 + e1;
            }
            s += __shfl_xor_sync(0xffffffffu, s, 1);
            s += __shfl_xor_sync(0xffffffffu, s, 2);
            if ((lane & 3) == 0) smr[wn * 64 + row] = s;
        }
    asm volatile("cp.async.wait_group 0;\n" ::: "memory");
    __syncthreads();   // barrier 2

    // ---- phase 3: O_partial = P V ----
    float acc3[2][4][4];
#pragma unroll
    for (int mt = 0; mt < 2; mt++)
#pragma unroll
        for (int nt = 0; nt < 4; nt++)
#pragma unroll
            for (int r = 0; r < 4; r++) acc3[mt][nt][r] = 0.f;

#pragma unroll
    for (int kt = 0; kt < KT; kt++) {
        uint32_t bh3[4][2], bl3[4][2];
#pragma unroll
        for (int nt3 = 0; nt3 < 4; nt3++) {
            const int e = nt3 * 8 + g;
            const int base = e * VSP + wn * SCH + kt * 16 + qk;
            bh3[nt3][0] = *(const uint32_t*)&Vh[base];
            bh3[nt3][1] = *(const uint32_t*)&Vh[base + 8];
            bl3[nt3][0] = *(const uint32_t*)&Vl[base];
            bl3[nt3][1] = *(const uint32_t*)&Vl[base + 8];
        }
#pragma unroll
        for (int mt = 0; mt < 2; mt++) {
            uint32_t ah[4], al[4];
            pack2_hilo(acc[mt][2 * kt][0],     acc[mt][2 * kt][1],     ah[0], al[0]);
            pack2_hilo(acc[mt][2 * kt][2],     acc[mt][2 * kt][3],     ah[1], al[1]);
            pack2_hilo(acc[mt][2 * kt + 1][0], acc[mt][2 * kt + 1][1], ah[2], al[2]);
            pack2_hilo(acc[mt][2 * kt + 1][2], acc[mt][2 * kt + 1][3], ah[3], al[3]);
#pragma unroll
            for (int nt3 = 0; nt3 < 4; nt3++) {
                mma16816(acc3[mt][nt3], ah, bh3[nt3]);
                mma16816(acc3[mt][nt3], al, bh3[nt3]);
                mma16816(acc3[mt][nt3], ah, bl3[nt3]);
            }
        }
    }

    // write partials (slot = wn*2 + wm)
#pragma unroll
    for (int mt = 0; mt < 2; mt++)
#pragma unroll
        for (int nt3 = 0; nt3 < 4; nt3++) {
            const int rl = mt * 16 + g;
            const int base = ((wn * 2 + wm) * 32 + rl) * 34 + nt3 * 8 + qk;
            *(float2*)&pb[base] = make_float2(acc3[mt][nt3][0], acc3[mt][nt3][1]);
            *(float2*)&pb[base + 8 * 34] = make_float2(acc3[mt][nt3][2], acc3[mt][nt3][3]);
        }
    __syncthreads();   // barrier 3

    // ---- reduction + epilogue ----
#pragma unroll
    for (int rr = 0; rr < 4; rr++) {
        const int rloc = rr * 8 + (lane >> 2);
        const int row = wm * 32 + rloc;
        const int cl = wn * 8 + (lane & 3) * 2;
        float ox = 0.f, oy = 0.f;
#pragma unroll
        for (int wv = 0; wv < 4; wv++) {
            float2 p = *(const float2*)&pb[((wv * 2 + wm) * 32 + rloc) * 34 + cl];
            ox += p.x; oy += p.y;
        }
        const float inv = 1.0f / (smr[row] + smr[64 + row] +
                                  smr[128 + row] + smr[192 + row]);
        const int col = ooff + h * 32 + cl;
        uint32_t hp, lp;
        pack2_hilo(ox * inv, oy * inv, hp, lp);
        *(uint32_t*)&cathi[((size_t)(b * 4096 + q0 + row)) * 256 + col] = hp;
        *(uint32_t*)&catlo[((size_t)(b * 4096 + q0 + row)) * 256 + col] = lp;
    }
}

__global__ __launch_bounds__(256, 2) void attn_b1(
    const __nv_bfloat16* __restrict__ qhi, const __nv_bfloat16* __restrict__ qlo,
    const __nv_bfloat16* __restrict__ khi, const __nv_bfloat16* __restrict__ klo,
    const __nv_bfloat16* __restrict__ vhi, const __nv_bfloat16* __restrict__ vlo,
    __nv_bfloat16* __restrict__ cathi, __nv_bfloat16* __restrict__ catlo)
{
    extern __shared__ char smc[];
    attn_body<256>(qhi, qlo, khi, klo, vhi, vlo, cathi, catlo, 0, 0, blockIdx.x, smc);
}

__global__ __launch_bounds__(256, 2) void attn_b2(
    const __nv_bfloat16* __restrict__ qhi, const __nv_bfloat16* __restrict__ qlo,
    const __nv_bfloat16* __restrict__ khi, const __nv_bfloat16* __restrict__ klo,
    const __nv_bfloat16* __restrict__ vhi, const __nv_bfloat16* __restrict__ vlo,
    __nv_bfloat16* __restrict__ cathi, __nv_bfloat16* __restrict__ catlo)
{
    extern __shared__ char smc[];
    attn_body<64>(qhi, qlo, khi, klo, vhi, vlo, cathi, catlo, 128, 128, blockIdx.x, smc);
}

// ---------------------------------------------------------------------------
// launch
// ---------------------------------------------------------------------------
extern "C" void kernel_launch(void* const* d_in, const int* in_sizes, int n_in,
                              void* d_out, int out_size)
{
    const float* x      = (const float*)d_in[0];
    const float* q_w    = (const float*)d_in[1];
    const float* kv1_w  = (const float*)d_in[2];
    const float* kv2_w  = (const float*)d_in[3];
    const float* proj_w = (const float*)d_in[4];
    const float* proj_b = (const float*)d_in[5];
    const float* sr1_w  = (const float*)d_in[6];
    const float* sr1_b  = (const float*)d_in[7];
    const float* sr2_w  = (const float*)d_in[8];
    const float* sr2_b  = (const float*)d_in[9];
    const float* ln1_g  = (const float*)d_in[10];
    const float* ln1_b  = (const float*)d_in[11];
    const float* ln2_g  = (const float*)d_in[12];
    const float* ln2_b  = (const float*)d_in[13];
    const float* lc1_w  = (const float*)d_in[14];
    const float* lc1_b  = (const float*)d_in[15];
    const float* lc2_w  = (const float*)d_in[16];
    const float* lc2_b  = (const float*)d_in[17];
    float* out = (float*)d_out;

    __nv_bfloat16 *p_xhi, *p_xlo, *p_qhi, *p_qlo, *p_cathi, *p_catlo;
    __nv_bfloat16 *p_x1hi, *p_x1lo, *p_x2hi, *p_x2lo;
    __nv_bfloat16 *p_k1hi, *p_k1lo, *p_k2hi, *p_k2lo;
    __nv_bfloat16 *p_v1hi, *p_v1lo, *p_v2hi, *p_v2lo;
    float *p_kv1, *p_kv2;
    __nv_bfloat16 *p_qwh, *p_qwl, *p_k1wh, *p_k1wl, *p_k2wh, *p_k2wl, *p_pwh, *p_pwl;
    cudaGetSymbolAddress((void**)&p_xhi,   g_xhi);
    cudaGetSymbolAddress((void**)&p_xlo,   g_xlo);
    cudaGetSymbolAddress((void**)&p_qhi,   g_qhi);
    cudaGetSymbolAddress((void**)&p_qlo,   g_qlo);
    cudaGetSymbolAddress((void**)&p_cathi, g_cathi);
    cudaGetSymbolAddress((void**)&p_catlo, g_catlo);
    cudaGetSymbolAddress((void**)&p_x1hi,  g_x1hi);
    cudaGetSymbolAddress((void**)&p_x1lo,  g_x1lo);
    cudaGetSymbolAddress((void**)&p_x2hi,  g_x2hi);
    cudaGetSymbolAddress((void**)&p_x2lo,  g_x2lo);
    cudaGetSymbolAddress((void**)&p_kv1,   g_kv1);
    cudaGetSymbolAddress((void**)&p_kv2,   g_kv2);
    cudaGetSymbolAddress((void**)&p_k1hi,  g_k1hi);
    cudaGetSymbolAddress((void**)&p_k1lo,  g_k1lo);
    cudaGetSymbolAddress((void**)&p_k2hi,  g_k2hi);
    cudaGetSymbolAddress((void**)&p_k2lo,  g_k2lo);
    cudaGetSymbolAddress((void**)&p_v1hi,  g_v1hi);
    cudaGetSymbolAddress((void**)&p_v1lo,  g_v1lo);
    cudaGetSymbolAddress((void**)&p_v2hi,  g_v2hi);
    cudaGetSymbolAddress((void**)&p_v2lo,  g_v2lo);
    cudaGetSymbolAddress((void**)&p_qwh,   g_qwh);
    cudaGetSymbolAddress((void**)&p_qwl,   g_qwl);
    cudaGetSymbolAddress((void**)&p_k1wh,  g_k1wh);
    cudaGetSymbolAddress((void**)&p_k1wl,  g_k1wl);
    cudaGetSymbolAddress((void**)&p_k2wh,  g_k2wh);
    cudaGetSymbolAddress((void**)&p_k2wl,  g_k2wl);
    cudaGetSymbolAddress((void**)&p_pwh,   g_pwh);
    cudaGetSymbolAddress((void**)&p_pwl,   g_pwl);

    // gemm v1 smem: (Ahi+Alo 3x128x40 + Bh+Bl 3x256x40) bf16 = 184,320 B
    const int smem_gemm = (2 * 3 * 128 * 40 + 2 * 3 * 256 * 40) * 2;
    const int smem_dw   = 80 * 257 * 4 + 128;
    const int smem_a1   = 87040;   // NS=256 plane layout
    const int smem_a2   = 66560;   // NS=64 plane layout
    cudaFuncSetAttribute(gemm_all,  cudaFuncAttributeMaxDynamicSharedMemorySize, smem_gemm);
    cudaFuncSetAttribute(gemm_proj, cudaFuncAttributeMaxDynamicSharedMemorySize, smem_gemm);
    cudaFuncSetAttribute(dwconv_wsplit, cudaFuncAttributeMaxDynamicSharedMemorySize, smem_dw);
    cudaFuncSetAttribute(attn_b1, cudaFuncAttributeMaxDynamicSharedMemorySize, smem_a1);
    cudaFuncSetAttribute(attn_b2, cudaFuncAttributeMaxDynamicSharedMemorySize, smem_a2);

    // 0: dwconv (+x planes) + weight split
    dwconv_wsplit<<<768, 512, smem_dw>>>(
        x, p_xhi, p_xlo,
        sr1_w, sr1_b, ln1_g, ln1_b, sr2_w, sr2_b, ln2_g, ln2_b,
        p_x1hi, p_x1lo, p_x2hi, p_x2lo,
        q_w, kv1_w, kv2_w, proj_w,
        p_qwh, p_qwl, p_k1wh, p_k1wl, p_k2wh, p_k2wl, p_pwh, p_pwl);
    // 1: all projections (q 256 + kv1 16 + kv2 4 blocks)
    gemm_all<<<276, 512, smem_gemm>>>(
        p_xhi, p_xlo, p_x1hi, p_x1lo, p_x2hi, p_x2lo,
        p_qwh, p_qwl, p_k1wh, p_k1wl, p_k2wh, p_k2wl,
        p_qhi, p_qlo, p_kv1, p_k1hi, p_k1lo, p_kv2, p_k2hi, p_k2lo);
    // 2: v local conv -> V^T planes
    vconv_fused<<<BATCH * 256 + BATCH * 64, 128>>>(
        p_kv1, lc1_w, lc1_b, p_v1hi, p_v1lo,
        p_kv2, lc2_w, lc2_b, p_v2hi, p_v2lo);
    // 3: attention branch 1 (PROFILED SLOT)
    attn_b1<<<dim3(32, 64), 256, smem_a1>>>(
        p_qhi, p_qlo, p_k1hi, p_k1lo, p_v1hi, p_v1lo, p_cathi, p_catlo);
    // 4: attention branch 2
    attn_b2<<<dim3(32, 64), 256, smem_a2>>>(
        p_qhi, p_qlo, p_k2hi, p_k2lo, p_v2hi, p_v2lo, p_cathi, p_catlo);
    // 5: output projection
    gemm_proj<<<256, 512, smem_gemm>>>(p_cathi, p_catlo, p_pwh, p_pwl, proj_b, out);
}

// round 13
// speedup vs baseline: 1.0839x; 1.0839x over previous
#include <cuda_runtime.h>
#include <cuda_bf16.h>
#include <cstdint>

// Problem constants: B=8, H=W=64, N=4096, C=256, nh=8, nh2=4, hd=32, sr=8
#define BATCH 8
#define NTOK 4096
#define CH 256

// ---------------------------------------------------------------------------
// Scratch (device globals) — round-9 packed (hi,lo)-u32 format
// ---------------------------------------------------------------------------
__device__ uint32_t g_xp  [(size_t)BATCH * NTOK * CH];
__device__ uint32_t g_qp  [(size_t)BATCH * NTOK * CH];
__device__ uint32_t g_catp[(size_t)BATCH * NTOK * CH];
__device__ uint32_t g_x1p [BATCH * 256 * CH];
__device__ uint32_t g_x2p [BATCH * 64 * CH];
__device__ float    g_kv1 [BATCH * 256 * CH];
__device__ float    g_kv2 [BATCH * 64 * CH];
__device__ uint32_t g_k1p [BATCH * 256 * 128];
__device__ uint32_t g_k2p [BATCH * 64 * 128];
__device__ uint32_t g_v1p [BATCH * 4 * 32 * 256];        // V^T packed [b,h][e][s]
__device__ uint32_t g_v2p [BATCH * 4 * 32 * 64];
// weight splits (hi/lo planes)
__device__ __nv_bfloat16 g_qwh [256 * 256], g_qwl [256 * 256];
__device__ __nv_bfloat16 g_k1wh[256 * 256], g_k1wl[256 * 256];
__device__ __nv_bfloat16 g_k2wh[256 * 256], g_k2wl[256 * 256];
__device__ __nv_bfloat16 g_pwh [256 * 256], g_pwl [256 * 256];

// ---------------------------------------------------------------------------
// helpers
// ---------------------------------------------------------------------------
__device__ __forceinline__ uint32_t pack_hilo(float v) {
    __nv_bfloat16 h = __float2bfloat16(v);
    __nv_bfloat16 l = __float2bfloat16(v - __bfloat162float(h));
    return (uint32_t)__bfloat16_as_ushort(h) |
           ((uint32_t)__bfloat16_as_ushort(l) << 16);
}

__device__ __forceinline__ void pack2_hilo(
    float p0, float p1, uint32_t& h, uint32_t& l)
{
    uint32_t hp;
    asm("cvt.rn.bf16x2.f32 %0, %1, %2;" : "=r"(hp) : "f"(p1), "f"(p0));
    const float r0 = p0 - __uint_as_float(hp << 16);
    const float r1 = p1 - __uint_as_float(hp & 0xffff0000u);
    uint32_t lp;
    asm("cvt.rn.bf16x2.f32 %0, %1, %2;" : "=r"(lp) : "f"(r1), "f"(r0));
    h = hp; l = lp;
}

__device__ __forceinline__ void mma16816(
    float* c, const uint32_t* a, const uint32_t* b)
{
    asm volatile(
        "mma.sync.aligned.m16n8k16.row.col.f32.bf16.bf16.f32 "
        "{%0,%1,%2,%3}, {%4,%5,%6,%7}, {%8,%9}, {%0,%1,%2,%3};"
        : "+f"(c[0]), "+f"(c[1]), "+f"(c[2]), "+f"(c[3])
        : "r"(a[0]), "r"(a[1]), "r"(a[2]), "r"(a[3]), "r"(b[0]), "r"(b[1]));
}

__device__ __forceinline__ void cpa16(void* dst, const void* src) {
    uint32_t d = (uint32_t)__cvta_generic_to_shared(dst);
    asm volatile("cp.async.cg.shared.global [%0], [%1], 16;\n"
                 :: "r"(d), "l"(src));
}

// ---------------------------------------------------------------------------
// GEMM body v1 (round-9, best measured): 512 threads, 128x256 tile,
// 3-stage cp.async. A packed u32; W hi/lo planes. 16 warps = 4m x 4n.
// MODE 0: fp32 out (+bias). MODE 1: packed out. MODE 2: fp32 + packed k-half.
// ---------------------------------------------------------------------------
template<int MODE>
__device__ __forceinline__ void gemm_body(
    const uint32_t* __restrict__ A,
    const __nv_bfloat16* __restrict__ Wh,
    const __nv_bfloat16* __restrict__ Wl,
    const float* __restrict__ bias,
    float* __restrict__ Cf, uint32_t* __restrict__ Cp,
    int m0, char* smraw)
{
    constexpr int LDA = 40;
    constexpr int LDB = 40;
    constexpr int ASZ = 128 * LDA;
    constexpr int BSZ = 256 * LDB;

    uint32_t*      Ap = (uint32_t*)smraw;
    __nv_bfloat16* Bh = (__nv_bfloat16*)(Ap + 3 * ASZ);
    __nv_bfloat16* Bl = Bh + 3 * BSZ;

    const int tid = threadIdx.x;
    const int w = tid >> 5, lane = tid & 31;
    const int wm = w & 3, wn = w >> 2;
    const int g = lane >> 2, qk = (lane & 3) * 2;

    auto load_stage = [&](int s, int k0) {
#pragma unroll
        for (int i = 0; i < 2; i++) {
            const int c = tid + i * 512;
            const int row = c >> 3, ch = c & 7;
            cpa16(&Ap[s * ASZ + row * LDA + ch * 4],
                  &A[(size_t)(m0 + row) * 256 + k0 + ch * 4]);
        }
#pragma unroll
        for (int i = 0; i < 2; i++) {
            const int c = tid + i * 512;
            const int row = c >> 2, ch = c & 3;
            cpa16(&Bh[s * BSZ + row * LDB + ch * 8],
                  &Wh[(size_t)row * 256 + k0 + ch * 8]);
        }
#pragma unroll
        for (int i = 0; i < 2; i++) {
            const int c = tid + i * 512;
            const int row = c >> 2, ch = c & 3;
            cpa16(&Bl[s * BSZ + row * LDB + ch * 8],
                  &Wl[(size_t)row * 256 + k0 + ch * 8]);
        }
        asm volatile("cp.async.commit_group;\n" ::: "memory");
    };

    float acc[2][8][4];
#pragma unroll
    for (int mt = 0; mt < 2; mt++)
#pragma unroll
        for (int nt = 0; nt < 8; nt++)
#pragma unroll
            for (int r = 0; r < 4; r++) acc[mt][nt][r] = 0.f;

    load_stage(0, 0);
    load_stage(1, 32);

    for (int it = 0; it < 8; it++) {
        if (it < 7) asm volatile("cp.async.wait_group 1;\n" ::: "memory");
        else        asm volatile("cp.async.wait_group 0;\n" ::: "memory");
        __syncthreads();
        if (it + 2 < 8) load_stage((it + 2) % 3, (it + 2) * 32);

        const int s = it % 3;
        const uint32_t*      As  = Ap + s * ASZ;
        const __nv_bfloat16* Bhs = Bh + s * BSZ;
        const __nv_bfloat16* Bls = Bl + s * BSZ;

#pragma unroll
        for (int ks = 0; ks < 2; ks++) {
            const int kb = ks * 16;
            uint32_t ah[2][4], al[2][4];
#pragma unroll
            for (int mt = 0; mt < 2; mt++) {
                const int row = wm * 32 + mt * 16 + g;
                uint2 p0 = *(const uint2*)&As[row * LDA + kb + qk];
                uint2 p1 = *(const uint2*)&As[(row + 8) * LDA + kb + qk];
                uint2 p2 = *(const uint2*)&As[row * LDA + kb + qk + 8];
                uint2 p3 = *(const uint2*)&As[(row + 8) * LDA + kb + qk + 8];
                ah[mt][0] = __byte_perm(p0.x, p0.y, 0x5410);
                al[mt][0] = __byte_perm(p0.x, p0.y, 0x7632);
                ah[mt][1] = __byte_perm(p1.x, p1.y, 0x5410);
                al[mt][1] = __byte_perm(p1.x, p1.y, 0x7632);
                ah[mt][2] = __byte_perm(p2.x, p2.y, 0x5410);
                al[mt][2] = __byte_perm(p2.x, p2.y, 0x7632);
                ah[mt][3] = __byte_perm(p3.x, p3.y, 0x5410);
                al[mt][3] = __byte_perm(p3.x, p3.y, 0x7632);
            }
            uint32_t bf[8][2];
#pragma unroll
            for (int nt = 0; nt < 8; nt++) {
                const __nv_bfloat16* pb = &Bhs[(wn * 64 + nt * 8 + g) * LDB + kb + qk];
                bf[nt][0] = *(const uint32_t*)pb;
                bf[nt][1] = *(const uint32_t*)(pb + 8);
            }
#pragma unroll
            for (int mt = 0; mt < 2; mt++)
#pragma unroll
                for (int nt = 0; nt < 8; nt++) {
                    mma16816(acc[mt][nt], ah[mt], bf[nt]);
                    mma16816(acc[mt][nt], al[mt], bf[nt]);
                }
#pragma unroll
            for (int nt = 0; nt < 8; nt++) {
                const __nv_bfloat16* pb = &Bls[(wn * 64 + nt * 8 + g) * LDB + kb + qk];
                bf[nt][0] = *(const uint32_t*)pb;
                bf[nt][1] = *(const uint32_t*)(pb + 8);
            }
#pragma unroll
            for (int mt = 0; mt < 2; mt++)
#pragma unroll
                for (int nt = 0; nt < 8; nt++)
                    mma16816(acc[mt][nt], ah[mt], bf[nt]);
        }
        __syncthreads();
    }

#pragma unroll
    for (int mt = 0; mt < 2; mt++) {
        const int r = m0 + wm * 32 + mt * 16 + g;
#pragma unroll
        for (int nt = 0; nt < 8; nt++) {
            const int col = wn * 64 + nt * 8 + qk;
            if constexpr (MODE == 0) {
                const float b0 = bias[col], b1 = bias[col + 1];
                *(float2*)&Cf[(size_t)r * 256 + col] =
                    make_float2(acc[mt][nt][0] + b0, acc[mt][nt][1] + b1);
                *(float2*)&Cf[(size_t)(r + 8) * 256 + col] =
                    make_float2(acc[mt][nt][2] + b0, acc[mt][nt][3] + b1);
            } else if constexpr (MODE == 1) {
                *(uint2*)&Cp[(size_t)r * 256 + col] =
                    make_uint2(pack_hilo(acc[mt][nt][0]), pack_hilo(acc[mt][nt][1]));
                *(uint2*)&Cp[(size_t)(r + 8) * 256 + col] =
                    make_uint2(pack_hilo(acc[mt][nt][2]), pack_hilo(acc[mt][nt][3]));
            } else {
                *(float2*)&Cf[(size_t)r * 256 + col] =
                    make_float2(acc[mt][nt][0], acc[mt][nt][1]);
                *(float2*)&Cf[(size_t)(r + 8) * 256 + col] =
                    make_float2(acc[mt][nt][2], acc[mt][nt][3]);
                if (col < 128) {
                    *(uint2*)&Cp[(size_t)r * 128 + col] =
                        make_uint2(pack_hilo(acc[mt][nt][0]), pack_hilo(acc[mt][nt][1]));
                    *(uint2*)&Cp[(size_t)(r + 8) * 128 + col] =
                        make_uint2(pack_hilo(acc[mt][nt][2]), pack_hilo(acc[mt][nt][3]));
                }
            }
        }
    }
}

// Combined projection GEMMs: q (256 blocks) + kv1 (16) + kv2 (4).
__global__ __launch_bounds__(512) void gemm_all(
    const uint32_t* __restrict__ xp,
    const uint32_t* __restrict__ x1p, const uint32_t* __restrict__ x2p,
    const __nv_bfloat16* __restrict__ qwh, const __nv_bfloat16* __restrict__ qwl,
    const __nv_bfloat16* __restrict__ k1wh, const __nv_bfloat16* __restrict__ k1wl,
    const __nv_bfloat16* __restrict__ k2wh, const __nv_bfloat16* __restrict__ k2wl,
    uint32_t* __restrict__ qp,
    float* __restrict__ kv1, uint32_t* __restrict__ k1p,
    float* __restrict__ kv2, uint32_t* __restrict__ k2p)
{
    extern __shared__ __align__(16) char smraw[];
    if (blockIdx.x < 256)
        gemm_body<1>(xp, qwh, qwl, nullptr, nullptr, qp, blockIdx.x * 128, smraw);
    else if (blockIdx.x < 272)
        gemm_body<2>(x1p, k1wh, k1wl, nullptr, kv1, k1p, (blockIdx.x - 256) * 128, smraw);
    else
        gemm_body<2>(x2p, k2wh, k2wl, nullptr, kv2, k2p, (blockIdx.x - 272) * 128, smraw);
}

// Output projection.
__global__ __launch_bounds__(512) void gemm_proj(
    const uint32_t* __restrict__ A,
    const __nv_bfloat16* __restrict__ Wh, const __nv_bfloat16* __restrict__ Wl,
    const float* __restrict__ bias, float* __restrict__ Cf)
{
    extern __shared__ __align__(16) char smraw[];
    gemm_body<0>(A, Wh, Wl, bias, Cf, nullptr, blockIdx.x * 128, smraw);
}

// ---------------------------------------------------------------------------
// LN + exact GELU block helper (per 256-thread window group)
// ---------------------------------------------------------------------------
__device__ __forceinline__ float ln_gelu_block(
    float a, const float* __restrict__ g, const float* __restrict__ bln,
    float* red, int c)
{
    float s1 = a, s2 = a * a;
#pragma unroll
    for (int o = 16; o > 0; o >>= 1) {
        s1 += __shfl_xor_sync(0xffffffffu, s1, o);
        s2 += __shfl_xor_sync(0xffffffffu, s2, o);
    }
    if ((c & 31) == 0) { red[c >> 5] = s1; red[8 + (c >> 5)] = s2; }
    __syncthreads();
    if (c == 0) {
        float a0 = 0.f, b0 = 0.f;
#pragma unroll
        for (int i = 0; i < 8; i++) { a0 += red[i]; b0 += red[8 + i]; }
        red[0] = a0; red[8] = b0;
    }
    __syncthreads();
    const float mean = red[0] * (1.f / 256.f);
    const float var  = red[8] * (1.f / 256.f) - mean * mean;
    float y = (a - mean) * rsqrtf(var + 1e-5f) * g[c] + bln[c];
    y = 0.5f * y * (1.0f + erff(y * 0.70710678118654752f));
    __syncthreads();
    return y;
}

// ---------------------------------------------------------------------------
// dwconv_fused + x-pack + weight split (round-9, verified)
// ---------------------------------------------------------------------------
__global__ __launch_bounds__(512) void dwconv_wsplit(
    const float* __restrict__ x, uint32_t* __restrict__ xp,
    const float* __restrict__ w1, const float* __restrict__ b1c,
    const float* __restrict__ g1, const float* __restrict__ bl1,
    const float* __restrict__ w2, const float* __restrict__ b2c,
    const float* __restrict__ g2, const float* __restrict__ bl2,
    uint32_t* __restrict__ x1p, uint32_t* __restrict__ x2p,
    const float* __restrict__ w0m, const float* __restrict__ w1m,
    const float* __restrict__ w2m, const float* __restrict__ w3m,
    __nv_bfloat16* __restrict__ h0, __nv_bfloat16* __restrict__ l0,
    __nv_bfloat16* __restrict__ h1, __nv_bfloat16* __restrict__ l1,
    __nv_bfloat16* __restrict__ h2, __nv_bfloat16* __restrict__ l2,
    __nv_bfloat16* __restrict__ h3, __nv_bfloat16* __restrict__ l3)
{
    if (blockIdx.x >= 256) {
        const int widx = blockIdx.x - 256;
        const int which = widx >> 7;
        const int i = (widx & 127) * 512 + threadIdx.x;
        const float* in = which == 0 ? w0m : which == 1 ? w1m : which == 2 ? w2m : w3m;
        __nv_bfloat16* oh = which == 0 ? h0 : which == 1 ? h1 : which == 2 ? h2 : h3;
        __nv_bfloat16* ol = which == 0 ? l0 : which == 1 ? l1 : which == 2 ? l2 : l3;
        const float v = in[i];
        const __nv_bfloat16 hi = __float2bfloat16(v);
        oh[i] = hi;
        ol[i] = __float2bfloat16(v - __bfloat162float(hi));
        return;
    }

    extern __shared__ float sw[];
    float* w2s = sw;
    float* w1s = sw + 64 * 257;
    float* redb = sw + 80 * 257;

    const int tid = threadIdx.x;
    const int c = tid & 255;
    const int win = tid >> 8;
    float* red = redb + win * 16;

    const int b = blockIdx.x >> 5;
    const int pair = blockIdx.x & 31;
    const int t2 = pair * 2 + win;
    const int oh2 = t2 >> 3, ow2 = t2 & 7;

    for (int i = tid; i < 64 * 256; i += 512)
        w2s[(i & 63) * 257 + (i >> 6)] = w2[i];
    for (int i = tid; i < 16 * 256; i += 512)
        w1s[(i & 15) * 257 + (i >> 4)] = w1[i];
    __syncthreads();

    float acc2 = b2c[c];
    float acc1[2][2];
    acc1[0][0] = acc1[0][1] = acc1[1][0] = acc1[1][1] = b1c[c];

#pragma unroll
    for (int kh = 0; kh < 8; kh++) {
#pragma unroll
        for (int kw = 0; kw < 8; kw++) {
            const int ih = oh2 * 8 + kh, iw = ow2 * 8 + kw;
            const size_t xi = ((size_t)b * NTOK + ih * 64 + iw) * CH + c;
            const float xv = x[xi];
            xp[xi] = pack_hilo(xv);
            acc2 += xv * w2s[(kh * 8 + kw) * 257 + c];
            acc1[kh >> 2][kw >> 2] += xv * w1s[((kh & 3) * 4 + (kw & 3)) * 257 + c];
        }
    }

    const float y2 = ln_gelu_block(acc2, g2, bl2, red, c);
    x2p[((size_t)b * 64 + t2) * CH + c] = pack_hilo(y2);
#pragma unroll
    for (int i = 0; i < 2; i++)
#pragma unroll
        for (int j = 0; j < 2; j++) {
            const float y1 = ln_gelu_block(acc1[i][j], g1, bl1, red, c);
            const int t1 = (oh2 * 2 + i) * 16 + (ow2 * 2 + j);
            x1p[((size_t)b * 256 + t1) * CH + c] = pack_hilo(y1);
        }
}

// ---------------------------------------------------------------------------
// Fused v local conv (+residual) -> packed V^T [b,h][e][s] (round-9)
// ---------------------------------------------------------------------------
__global__ __launch_bounds__(128) void vconv_fused(
    const float* __restrict__ kv1, const float* __restrict__ lcw1,
    const float* __restrict__ lcb1, uint32_t* __restrict__ v1p,
    const float* __restrict__ kv2, const float* __restrict__ lcw2,
    const float* __restrict__ lcb2, uint32_t* __restrict__ v2p)
{
    int token, HS;
    const float *kv, *lcw, *lcb;
    uint32_t* vtp;
    if (blockIdx.x < BATCH * 256) {
        token = blockIdx.x; HS = 16; kv = kv1; lcw = lcw1; lcb = lcb1; vtp = v1p;
    } else {
        token = blockIdx.x - BATCH * 256; HS = 8; kv = kv2; lcw = lcw2; lcb = lcb2; vtp = v2p;
    }
    const int NS = HS * HS;
    const int b  = token / NS;
    const int s  = token - b * NS;
    const int hs = s / HS, ws = s - hs * HS;
    const int c  = threadIdx.x;

    float acc = lcb[c];
#pragma unroll
    for (int kh = 0; kh < 3; kh++)
#pragma unroll
        for (int kw = 0; kw < 3; kw++) {
            const int ih = hs - 1 + kh, iw = ws - 1 + kw;
            if (ih >= 0 && ih < HS && iw >= 0 && iw < HS)
                acc += kv[((size_t)b * NS + ih * HS + iw) * 256 + 128 + c]
                     * lcw[c * 9 + kh * 3 + kw];
        }
    const float v = kv[(size_t)token * 256 + 128 + c] + acc;
    const int h = c >> 5, e = c & 31;
    vtp[(((size_t)b * 4 + h) * 32 + e) * NS + s] = pack_hilo(v);
}

// ---------------------------------------------------------------------------
// Flash attention (round-9 structure). 64 q / 256 threads / 2 blocks per SM.
// CHANGE vs round 9: phase-1 QK^T uses HI-ONLY operands (1 mma per tile,
// was 3). Logits sigma ~0.07 => score error ~1e-3 abs -> p err ~2e-4 rel.
// PV keeps the full 3-term split.
// ---------------------------------------------------------------------------
template<int NS>
__device__ __forceinline__ void attn_body(
    const uint32_t* __restrict__ qp,
    const uint32_t* __restrict__ kp,
    const uint32_t* __restrict__ vtp,
    uint32_t* __restrict__ catp,
    int qoff, int ooff, int bh, float* smf)
{
    constexpr int SCH = NS / 4;
    constexpr int NT2 = SCH / 8;
    constexpr int KT  = SCH / 16;
    constexpr int LDQ = 36;
    constexpr int VSP = NS + 4;
    constexpr int CHK = NS / 4;
    constexpr int OFF_KS = 64 * LDQ;
    constexpr int OFF_VS = OFF_KS + NS * LDQ;
    constexpr int VEND   = OFF_VS + 32 * VSP;
    constexpr int OFF_PB = (OFF_VS >= 8704) ? 0 : VEND;
    constexpr int PBEND  = OFF_PB + 8 * 32 * 34;
    constexpr int OFF_ST = (PBEND > VEND) ? PBEND : VEND;
    const float kfac = 0.17677669529663689f * 1.4426950408889634f;

    uint32_t* SM  = (uint32_t*)smf;
    uint32_t* Qs  = SM;
    uint32_t* Ks  = SM + OFF_KS;
    uint32_t* Vs  = SM + OFF_VS;
    float*    pb  = smf + OFF_PB;
    float*    mx  = smf + OFF_ST;
    float*    smr = smf + OFF_ST + 256;

    const int b = bh >> 2, h = bh & 3;
    const int q0 = blockIdx.y * 64;
    const int tid = threadIdx.x, lane = tid & 31, w = tid >> 5;
    const int g = lane >> 2, qk = (lane & 3) * 2;
    const int wm = w >> 2, wn = w & 3;

    // async staging: QK (group 0), V (group 1)
#pragma unroll 2
    for (int c = tid; c < 64 * 8; c += 256) {
        const int r = c >> 3, cw = c & 7;
        cpa16(&Qs[r * LDQ + cw * 4],
              &qp[((size_t)(b * 4096 + q0 + r)) * 256 + qoff + h * 32 + cw * 4]);
    }
    for (int c = tid; c < NS * 8; c += 256) {
        const int s = c >> 3, cw = c & 7;
        cpa16(&Ks[s * LDQ + cw * 4],
              &kp[((size_t)(b * NS + s)) * 128 + h * 32 + cw * 4]);
    }
    asm volatile("cp.async.commit_group;\n" ::: "memory");
    for (int c = tid; c < 32 * CHK; c += 256) {
        const int e = c / CHK, s4 = c % CHK;
        cpa16(&Vs[e * VSP + s4 * 4],
              &vtp[(((size_t)(b * 4 + h)) * 32 + e) * NS + s4 * 4]);
    }
    asm volatile("cp.async.commit_group;\n" ::: "memory");
    asm volatile("cp.async.wait_group 1;\n" ::: "memory");
    __syncthreads();

    // phase 1: S = Qhi Khi^T (hi-only)
    float acc[2][NT2][4];
#pragma unroll
    for (int mt = 0; mt < 2; mt++)
#pragma unroll
        for (int nt = 0; nt < NT2; nt++)
#pragma unroll
            for (int r = 0; r < 4; r++) acc[mt][nt][r] = 0.f;

#pragma unroll
    for (int kc = 0; kc < 2; kc++) {
        const int kb = kc * 16;
        uint32_t ah[2][4];
#pragma unroll
        for (int mt = 0; mt < 2; mt++) {
            const int row = wm * 32 + mt * 16 + g;
            uint2 p0 = *(const uint2*)&Qs[row * LDQ + kb + qk];
            uint2 p1 = *(const uint2*)&Qs[(row + 8) * LDQ + kb + qk];
            uint2 p2 = *(const uint2*)&Qs[row * LDQ + kb + qk + 8];
            uint2 p3 = *(const uint2*)&Qs[(row + 8) * LDQ + kb + qk + 8];
            ah[mt][0] = __byte_perm(p0.x, p0.y, 0x5410);
            ah[mt][1] = __byte_perm(p1.x, p1.y, 0x5410);
            ah[mt][2] = __byte_perm(p2.x, p2.y, 0x5410);
            ah[mt][3] = __byte_perm(p3.x, p3.y, 0x5410);
        }
#pragma unroll
        for (int nt = 0; nt < NT2; nt++) {
            const int srow = wn * SCH + nt * 8 + g;
            uint2 p0 = *(const uint2*)&Ks[srow * LDQ + kb + qk];
            uint2 p1 = *(const uint2*)&Ks[srow * LDQ + kb + qk + 8];
            uint32_t bh2[2];
            bh2[0] = __byte_perm(p0.x, p0.y, 0x5410);
            bh2[1] = __byte_perm(p1.x, p1.y, 0x5410);
#pragma unroll
            for (int mt = 0; mt < 2; mt++)
                mma16816(acc[mt][nt], ah[mt], bh2);
        }
    }

    // chunk max
#pragma unroll
    for (int mt = 0; mt < 2; mt++)
#pragma unroll
        for (int half = 0; half < 2; half++) {
            float m = acc[mt][0][half * 2];
#pragma unroll
            for (int nt = 0; nt < NT2; nt++) {
                m = fmaxf(m, acc[mt][nt][half * 2]);
                m = fmaxf(m, acc[mt][nt][half * 2 + 1]);
            }
            m = fmaxf(m, __shfl_xor_sync(0xffffffffu, m, 1));
            m = fmaxf(m, __shfl_xor_sync(0xffffffffu, m, 2));
            if ((lane & 3) == 0)
                mx[wn * 64 + wm * 32 + mt * 16 + half * 8 + g] = m;
        }
    __syncthreads();   // barrier 1

    // global max, exp, chunk sums
#pragma unroll
    for (int mt = 0; mt < 2; mt++)
#pragma unroll
        for (int half = 0; half < 2; half++) {
            const int row = wm * 32 + mt * 16 + half * 8 + g;
            float m = fmaxf(fmaxf(mx[row], mx[64 + row]),
                            fmaxf(mx[128 + row], mx[192 + row]));
            float s = 0.f;
#pragma unroll
            for (int nt = 0; nt < NT2; nt++) {
                float e0 = exp2f((acc[mt][nt][half * 2]     - m) * kfac);
                float e1 = exp2f((acc[mt][nt][half * 2 + 1] - m) * kfac);
                acc[mt][nt][half * 2]     = e0;
                acc[mt][nt][half * 2 + 1] = e1;
                s += e0 + e1;
            }
            s += __shfl_xor_sync(0xffffffffu, s, 1);
            s += __shfl_xor_sync(0xffffffffu, s, 2);
            if ((lane & 3) == 0) smr[wn * 64 + row] = s;
        }
    asm volatile("cp.async.wait_group 0;\n" ::: "memory");
    __syncthreads();   // barrier 2

    // phase 3: O_partial = P V (full 3-term split)
    float acc3[2][4][4];
#pragma unroll
    for (int mt = 0; mt < 2; mt++)
#pragma unroll
        for (int nt = 0; nt < 4; nt++)
#pragma unroll
            for (int r = 0; r < 4; r++) acc3[mt][nt][r] = 0.f;

#pragma unroll
    for (int kt = 0; kt < KT; kt++) {
        uint32_t bh3[4][2], bl3[4][2];
#pragma unroll
        for (int nt3 = 0; nt3 < 4; nt3++) {
            const int e = nt3 * 8 + g;
            const int base = e * VSP + wn * SCH + kt * 16 + qk;
            uint2 p0 = *(const uint2*)&Vs[base];
            uint2 p1 = *(const uint2*)&Vs[base + 8];
            bh3[nt3][0] = __byte_perm(p0.x, p0.y, 0x5410);
            bl3[nt3][0] = __byte_perm(p0.x, p0.y, 0x7632);
            bh3[nt3][1] = __byte_perm(p1.x, p1.y, 0x5410);
            bl3[nt3][1] = __byte_perm(p1.x, p1.y, 0x7632);
        }
#pragma unroll
        for (int mt = 0; mt < 2; mt++) {
            uint32_t ah[4], al[4];
            pack2_hilo(acc[mt][2 * kt][0],     acc[mt][2 * kt][1],     ah[0], al[0]);
            pack2_hilo(acc[mt][2 * kt][2],     acc[mt][2 * kt][3],     ah[1], al[1]);
            pack2_hilo(acc[mt][2 * kt + 1][0], acc[mt][2 * kt + 1][1], ah[2], al[2]);
            pack2_hilo(acc[mt][2 * kt + 1][2], acc[mt][2 * kt + 1][3], ah[3], al[3]);
#pragma unroll
            for (int nt3 = 0; nt3 < 4; nt3++) {
                mma16816(acc3[mt][nt3], ah, bh3[nt3]);
                mma16816(acc3[mt][nt3], al, bh3[nt3]);
                mma16816(acc3[mt][nt3], ah, bl3[nt3]);
            }
        }
    }

    // write partials (slot = wn*2 + wm)
#pragma unroll
    for (int mt = 0; mt < 2; mt++)
#pragma unroll
        for (int nt3 = 0; nt3 < 4; nt3++) {
            const int rl = mt * 16 + g;
            const int base = ((wn * 2 + wm) * 32 + rl) * 34 + nt3 * 8 + qk;
            *(float2*)&pb[base] = make_float2(acc3[mt][nt3][0], acc3[mt][nt3][1]);
            *(float2*)&pb[base + 8 * 34] = make_float2(acc3[mt][nt3][2], acc3[mt][nt3][3]);
        }
    __syncthreads();   // barrier 3

    // reduction + epilogue
#pragma unroll
    for (int rr = 0; rr < 4; rr++) {
        const int rloc = rr * 8 + (lane >> 2);
        const int row = wm * 32 + rloc;
        const int cl = wn * 8 + (lane & 3) * 2;
        float ox = 0.f, oy = 0.f;
#pragma unroll
        for (int wv = 0; wv < 4; wv++) {
            float2 p = *(const float2*)&pb[((wv * 2 + wm) * 32 + rloc) * 34 + cl];
            ox += p.x; oy += p.y;
        }
        const float inv = 1.0f / (smr[row] + smr[64 + row] +
                                  smr[128 + row] + smr[192 + row]);
        const int col = ooff + h * 32 + cl;
        *(uint2*)&catp[((size_t)(b * 4096 + q0 + row)) * 256 + col] =
            make_uint2(pack_hilo(ox * inv), pack_hilo(oy * inv));
    }
}

__global__ __launch_bounds__(256, 2) void attn_b1(
    const uint32_t* __restrict__ qp, const uint32_t* __restrict__ kp,
    const uint32_t* __restrict__ vtp, uint32_t* __restrict__ catp)
{
    extern __shared__ float smf[];
    attn_body<256>(qp, kp, vtp, catp, 0, 0, blockIdx.x, smf);
}

__global__ __launch_bounds__(256, 2) void attn_b2(
    const uint32_t* __restrict__ qp, const uint32_t* __restrict__ kp,
    const uint32_t* __restrict__ vtp, uint32_t* __restrict__ catp)
{
    extern __shared__ float smf[];
    attn_body<64>(qp, kp, vtp, catp, 128, 128, blockIdx.x, smf);
}

// ---------------------------------------------------------------------------
// launch
// ---------------------------------------------------------------------------
extern "C" void kernel_launch(void* const* d_in, const int* in_sizes, int n_in,
                              void* d_out, int out_size)
{
    const float* x      = (const float*)d_in[0];
    const float* q_w    = (const float*)d_in[1];
    const float* kv1_w  = (const float*)d_in[2];
    const float* kv2_w  = (const float*)d_in[3];
    const float* proj_w = (const float*)d_in[4];
    const float* proj_b = (const float*)d_in[5];
    const float* sr1_w  = (const float*)d_in[6];
    const float* sr1_b  = (const float*)d_in[7];
    const float* sr2_w  = (const float*)d_in[8];
    const float* sr2_b  = (const float*)d_in[9];
    const float* ln1_g  = (const float*)d_in[10];
    const float* ln1_b  = (const float*)d_in[11];
    const float* ln2_g  = (const float*)d_in[12];
    const float* ln2_b  = (const float*)d_in[13];
    const float* lc1_w  = (const float*)d_in[14];
    const float* lc1_b  = (const float*)d_in[15];
    const float* lc2_w  = (const float*)d_in[16];
    const float* lc2_b  = (const float*)d_in[17];
    float* out = (float*)d_out;

    uint32_t *p_xp, *p_qp, *p_catp, *p_x1p, *p_x2p, *p_k1p, *p_k2p, *p_v1p, *p_v2p;
    float *p_kv1, *p_kv2;
    __nv_bfloat16 *p_qwh, *p_qwl, *p_k1wh, *p_k1wl, *p_k2wh, *p_k2wl, *p_pwh, *p_pwl;
    cudaGetSymbolAddress((void**)&p_xp,   g_xp);
    cudaGetSymbolAddress((void**)&p_qp,   g_qp);
    cudaGetSymbolAddress((void**)&p_catp, g_catp);
    cudaGetSymbolAddress((void**)&p_x1p,  g_x1p);
    cudaGetSymbolAddress((void**)&p_x2p,  g_x2p);
    cudaGetSymbolAddress((void**)&p_kv1,  g_kv1);
    cudaGetSymbolAddress((void**)&p_kv2,  g_kv2);
    cudaGetSymbolAddress((void**)&p_k1p,  g_k1p);
    cudaGetSymbolAddress((void**)&p_k2p,  g_k2p);
    cudaGetSymbolAddress((void**)&p_v1p,  g_v1p);
    cudaGetSymbolAddress((void**)&p_v2p,  g_v2p);
    cudaGetSymbolAddress((void**)&p_qwh,  g_qwh);
    cudaGetSymbolAddress((void**)&p_qwl,  g_qwl);
    cudaGetSymbolAddress((void**)&p_k1wh, g_k1wh);
    cudaGetSymbolAddress((void**)&p_k1wl, g_k1wl);
    cudaGetSymbolAddress((void**)&p_k2wh, g_k2wh);
    cudaGetSymbolAddress((void**)&p_k2wl, g_k2wl);
    cudaGetSymbolAddress((void**)&p_pwh,  g_pwh);
    cudaGetSymbolAddress((void**)&p_pwl,  g_pwl);

    const int smem_gemm = 3 * (128 * 40 * 4) + 2 * (3 * 256 * 40 * 2);  // 184,320
    const int smem_dw   = 80 * 257 * 4 + 128;
    const int smem_a1   = 20352 * 4;   // NS=256 layout: 81,408 B
    const int smem_a2   = 16000 * 4;   // NS=64 layout:  64,000 B
    cudaFuncSetAttribute(gemm_all,  cudaFuncAttributeMaxDynamicSharedMemorySize, smem_gemm);
    cudaFuncSetAttribute(gemm_proj, cudaFuncAttributeMaxDynamicSharedMemorySize, smem_gemm);
    cudaFuncSetAttribute(dwconv_wsplit, cudaFuncAttributeMaxDynamicSharedMemorySize, smem_dw);
    cudaFuncSetAttribute(attn_b1, cudaFuncAttributeMaxDynamicSharedMemorySize, smem_a1);
    cudaFuncSetAttribute(attn_b2, cudaFuncAttributeMaxDynamicSharedMemorySize, smem_a2);

    // 0: dwconv (+x pack) + weight split
    dwconv_wsplit<<<768, 512, smem_dw>>>(
        x, p_xp, sr1_w, sr1_b, ln1_g, ln1_b, sr2_w, sr2_b, ln2_g, ln2_b,
        p_x1p, p_x2p,
        q_w, kv1_w, kv2_w, proj_w,
        p_qwh, p_qwl, p_k1wh, p_k1wl, p_k2wh, p_k2wl, p_pwh, p_pwl);
    // 1: all projections (q 256 + kv1 16 + kv2 4 blocks)
    gemm_all<<<276, 512, smem_gemm>>>(
        p_xp, p_x1p, p_x2p, p_qwh, p_qwl, p_k1wh, p_k1wl, p_k2wh, p_k2wl,
        p_qp, p_kv1, p_k1p, p_kv2, p_k2p);
    // 2: v local conv -> packed V^T
    vconv_fused<<<BATCH * 256 + BATCH * 64, 128>>>(
        p_kv1, lc1_w, lc1_b, p_v1p, p_kv2, lc2_w, lc2_b, p_v2p);
    // 3: attention branch 1 (PROFILED SLOT)
    attn_b1<<<dim3(32, 64), 256, smem_a1>>>(p_qp, p_k1p, p_v1p, p_catp);
    // 4: attention branch 2
    attn_b2<<<dim3(32, 64), 256, smem_a2>>>(p_qp, p_k2p, p_v2p, p_catp);
    // 5: output projection
    gemm_proj<<<256, 512, smem_gemm>>>(p_catp, p_pwh, p_pwl, proj_b, out);
}

// round 14
// speedup vs baseline: 1.1922x; 1.0999x over previous
#include <cuda_runtime.h>
#include <cuda_bf16.h>
#include <cstdint>

// Problem constants: B=8, H=W=64, N=4096, C=256, nh=8, nh2=4, hd=32, sr=8
#define BATCH 8
#define NTOK 4096
#define CH 256

// ---------------------------------------------------------------------------
// Scratch (device globals)
// ---------------------------------------------------------------------------
__device__ uint32_t      g_xp  [(size_t)BATCH * NTOK * CH];   // x packed (hi,lo)
__device__ __nv_bfloat16 g_qh  [(size_t)BATCH * NTOK * CH];   // q HI ONLY
__device__ uint32_t      g_catp[(size_t)BATCH * NTOK * CH];   // cat packed
__device__ uint32_t      g_x1p [BATCH * 256 * CH];
__device__ uint32_t      g_x2p [BATCH * 64 * CH];
__device__ float         g_kv1 [BATCH * 256 * CH];
__device__ float         g_kv2 [BATCH * 64 * CH];
__device__ __nv_bfloat16 g_k1h [BATCH * 256 * 128];           // k HI ONLY
__device__ __nv_bfloat16 g_k2h [BATCH * 64 * 128];
__device__ uint32_t      g_v1p [BATCH * 4 * 32 * 256];        // V^T packed
__device__ uint32_t      g_v2p [BATCH * 4 * 32 * 64];
// weight splits (hi/lo planes)
__device__ __nv_bfloat16 g_qwh [256 * 256], g_qwl [256 * 256];
__device__ __nv_bfloat16 g_k1wh[256 * 256], g_k1wl[256 * 256];
__device__ __nv_bfloat16 g_k2wh[256 * 256], g_k2wl[256 * 256];
__device__ __nv_bfloat16 g_pwh [256 * 256], g_pwl [256 * 256];

// ---------------------------------------------------------------------------
// helpers
// ---------------------------------------------------------------------------
__device__ __forceinline__ uint32_t pack_hilo(float v) {
    __nv_bfloat16 h = __float2bfloat16(v);
    __nv_bfloat16 l = __float2bfloat16(v - __bfloat162float(h));
    return (uint32_t)__bfloat16_as_ushort(h) |
           ((uint32_t)__bfloat16_as_ushort(l) << 16);
}

__device__ __forceinline__ uint32_t pack_hi2(float p0, float p1) {
    uint32_t hp;
    asm("cvt.rn.bf16x2.f32 %0, %1, %2;" : "=r"(hp) : "f"(p1), "f"(p0));
    return hp;
}

__device__ __forceinline__ void pack2_hilo(
    float p0, float p1, uint32_t& h, uint32_t& l)
{
    uint32_t hp;
    asm("cvt.rn.bf16x2.f32 %0, %1, %2;" : "=r"(hp) : "f"(p1), "f"(p0));
    const float r0 = p0 - __uint_as_float(hp << 16);
    const float r1 = p1 - __uint_as_float(hp & 0xffff0000u);
    uint32_t lp;
    asm("cvt.rn.bf16x2.f32 %0, %1, %2;" : "=r"(lp) : "f"(r1), "f"(r0));
    h = hp; l = lp;
}

__device__ __forceinline__ void mma16816(
    float* c, const uint32_t* a, const uint32_t* b)
{
    asm volatile(
        "mma.sync.aligned.m16n8k16.row.col.f32.bf16.bf16.f32 "
        "{%0,%1,%2,%3}, {%4,%5,%6,%7}, {%8,%9}, {%0,%1,%2,%3};"
        : "+f"(c[0]), "+f"(c[1]), "+f"(c[2]), "+f"(c[3])
        : "r"(a[0]), "r"(a[1]), "r"(a[2]), "r"(a[3]), "r"(b[0]), "r"(b[1]));
}

__device__ __forceinline__ void cpa16(void* dst, const void* src) {
    uint32_t d = (uint32_t)__cvta_generic_to_shared(dst);
    asm volatile("cp.async.cg.shared.global [%0], [%1], 16;\n"
                 :: "r"(d), "l"(src));
}

// ---------------------------------------------------------------------------
// GEMM body v1 (round-9/13 structure). 512 threads, 128x256 tile, 3-stage.
// MODE 0: fp32 out (+bias), 3-term.
// MODE 1: q -> bf16 HI out, 2-term (no Wl loads, no ah*Wl mma).
// MODE 2: fp32 out + k-half bf16 HI, 3-term.
// ---------------------------------------------------------------------------
template<int MODE>
__device__ __forceinline__ void gemm_body(
    const uint32_t* __restrict__ A,
    const __nv_bfloat16* __restrict__ Wh,
    const __nv_bfloat16* __restrict__ Wl,
    const float* __restrict__ bias,
    float* __restrict__ Cf, __nv_bfloat16* __restrict__ Cb,
    int m0, char* smraw)
{
    constexpr int LDA = 40;
    constexpr int LDB = 40;
    constexpr int ASZ = 128 * LDA;
    constexpr int BSZ = 256 * LDB;

    uint32_t*      Ap = (uint32_t*)smraw;
    __nv_bfloat16* Bh = (__nv_bfloat16*)(Ap + 3 * ASZ);
    __nv_bfloat16* Bl = Bh + 3 * BSZ;

    const int tid = threadIdx.x;
    const int w = tid >> 5, lane = tid & 31;
    const int wm = w & 3, wn = w >> 2;
    const int g = lane >> 2, qk = (lane & 3) * 2;

    auto load_stage = [&](int s, int k0) {
#pragma unroll
        for (int i = 0; i < 2; i++) {
            const int c = tid + i * 512;
            const int row = c >> 3, ch = c & 7;
            cpa16(&Ap[s * ASZ + row * LDA + ch * 4],
                  &A[(size_t)(m0 + row) * 256 + k0 + ch * 4]);
        }
#pragma unroll
        for (int i = 0; i < 2; i++) {
            const int c = tid + i * 512;
            const int row = c >> 2, ch = c & 3;
            cpa16(&Bh[s * BSZ + row * LDB + ch * 8],
                  &Wh[(size_t)row * 256 + k0 + ch * 8]);
        }
        if constexpr (MODE != 1) {
#pragma unroll
            for (int i = 0; i < 2; i++) {
                const int c = tid + i * 512;
                const int row = c >> 2, ch = c & 3;
                cpa16(&Bl[s * BSZ + row * LDB + ch * 8],
                      &Wl[(size_t)row * 256 + k0 + ch * 8]);
            }
        }
        asm volatile("cp.async.commit_group;\n" ::: "memory");
    };

    float acc[2][8][4];
#pragma unroll
    for (int mt = 0; mt < 2; mt++)
#pragma unroll
        for (int nt = 0; nt < 8; nt++)
#pragma unroll
            for (int r = 0; r < 4; r++) acc[mt][nt][r] = 0.f;

    load_stage(0, 0);
    load_stage(1, 32);

    for (int it = 0; it < 8; it++) {
        if (it < 7) asm volatile("cp.async.wait_group 1;\n" ::: "memory");
        else        asm volatile("cp.async.wait_group 0;\n" ::: "memory");
        __syncthreads();
        if (it + 2 < 8) load_stage((it + 2) % 3, (it + 2) * 32);

        const int s = it % 3;
        const uint32_t*      As  = Ap + s * ASZ;
        const __nv_bfloat16* Bhs = Bh + s * BSZ;
        const __nv_bfloat16* Bls = Bl + s * BSZ;

#pragma unroll
        for (int ks = 0; ks < 2; ks++) {
            const int kb = ks * 16;
            uint32_t ah[2][4], al[2][4];
#pragma unroll
            for (int mt = 0; mt < 2; mt++) {
                const int row = wm * 32 + mt * 16 + g;
                uint2 p0 = *(const uint2*)&As[row * LDA + kb + qk];
                uint2 p1 = *(const uint2*)&As[(row + 8) * LDA + kb + qk];
                uint2 p2 = *(const uint2*)&As[row * LDA + kb + qk + 8];
                uint2 p3 = *(const uint2*)&As[(row + 8) * LDA + kb + qk + 8];
                ah[mt][0] = __byte_perm(p0.x, p0.y, 0x5410);
                al[mt][0] = __byte_perm(p0.x, p0.y, 0x7632);
                ah[mt][1] = __byte_perm(p1.x, p1.y, 0x5410);
                al[mt][1] = __byte_perm(p1.x, p1.y, 0x7632);
                ah[mt][2] = __byte_perm(p2.x, p2.y, 0x5410);
                al[mt][2] = __byte_perm(p2.x, p2.y, 0x7632);
                ah[mt][3] = __byte_perm(p3.x, p3.y, 0x5410);
                al[mt][3] = __byte_perm(p3.x, p3.y, 0x7632);
            }
            uint32_t bf[8][2];
#pragma unroll
            for (int nt = 0; nt < 8; nt++) {
                const __nv_bfloat16* pb = &Bhs[(wn * 64 + nt * 8 + g) * LDB + kb + qk];
                bf[nt][0] = *(const uint32_t*)pb;
                bf[nt][1] = *(const uint32_t*)(pb + 8);
            }
#pragma unroll
            for (int mt = 0; mt < 2; mt++)
#pragma unroll
                for (int nt = 0; nt < 8; nt++) {
                    mma16816(acc[mt][nt], ah[mt], bf[nt]);
                    mma16816(acc[mt][nt], al[mt], bf[nt]);
                }
            if constexpr (MODE != 1) {
#pragma unroll
                for (int nt = 0; nt < 8; nt++) {
                    const __nv_bfloat16* pb = &Bls[(wn * 64 + nt * 8 + g) * LDB + kb + qk];
                    bf[nt][0] = *(const uint32_t*)pb;
                    bf[nt][1] = *(const uint32_t*)(pb + 8);
                }
#pragma unroll
                for (int mt = 0; mt < 2; mt++)
#pragma unroll
                    for (int nt = 0; nt < 8; nt++)
                        mma16816(acc[mt][nt], ah[mt], bf[nt]);
            }
        }
        __syncthreads();
    }

#pragma unroll
    for (int mt = 0; mt < 2; mt++) {
        const int r = m0 + wm * 32 + mt * 16 + g;
#pragma unroll
        for (int nt = 0; nt < 8; nt++) {
            const int col = wn * 64 + nt * 8 + qk;
            if constexpr (MODE == 0) {
                const float b0 = bias[col], b1 = bias[col + 1];
                *(float2*)&Cf[(size_t)r * 256 + col] =
                    make_float2(acc[mt][nt][0] + b0, acc[mt][nt][1] + b1);
                *(float2*)&Cf[(size_t)(r + 8) * 256 + col] =
                    make_float2(acc[mt][nt][2] + b0, acc[mt][nt][3] + b1);
            } else if constexpr (MODE == 1) {
                *(uint32_t*)&Cb[(size_t)r * 256 + col] =
                    pack_hi2(acc[mt][nt][0], acc[mt][nt][1]);
                *(uint32_t*)&Cb[(size_t)(r + 8) * 256 + col] =
                    pack_hi2(acc[mt][nt][2], acc[mt][nt][3]);
            } else {
                *(float2*)&Cf[(size_t)r * 256 + col] =
                    make_float2(acc[mt][nt][0], acc[mt][nt][1]);
                *(float2*)&Cf[(size_t)(r + 8) * 256 + col] =
                    make_float2(acc[mt][nt][2], acc[mt][nt][3]);
                if (col < 128) {
                    *(uint32_t*)&Cb[(size_t)r * 128 + col] =
                        pack_hi2(acc[mt][nt][0], acc[mt][nt][1]);
                    *(uint32_t*)&Cb[(size_t)(r + 8) * 128 + col] =
                        pack_hi2(acc[mt][nt][2], acc[mt][nt][3]);
                }
            }
        }
    }
}

// Combined projection GEMMs: q (256 blocks) + kv1 (16) + kv2 (4).
__global__ __launch_bounds__(512) void gemm_all(
    const uint32_t* __restrict__ xp,
    const uint32_t* __restrict__ x1p, const uint32_t* __restrict__ x2p,
    const __nv_bfloat16* __restrict__ qwh, const __nv_bfloat16* __restrict__ qwl,
    const __nv_bfloat16* __restrict__ k1wh, const __nv_bfloat16* __restrict__ k1wl,
    const __nv_bfloat16* __restrict__ k2wh, const __nv_bfloat16* __restrict__ k2wl,
    __nv_bfloat16* __restrict__ qh,
    float* __restrict__ kv1, __nv_bfloat16* __restrict__ k1h,
    float* __restrict__ kv2, __nv_bfloat16* __restrict__ k2h)
{
    extern __shared__ __align__(16) char smraw[];
    if (blockIdx.x < 256)
        gemm_body<1>(xp, qwh, qwl, nullptr, nullptr, qh, blockIdx.x * 128, smraw);
    else if (blockIdx.x < 272)
        gemm_body<2>(x1p, k1wh, k1wl, nullptr, kv1, k1h, (blockIdx.x - 256) * 128, smraw);
    else
        gemm_body<2>(x2p, k2wh, k2wl, nullptr, kv2, k2h, (blockIdx.x - 272) * 128, smraw);
}

// Output projection.
__global__ __launch_bounds__(512) void gemm_proj(
    const uint32_t* __restrict__ A,
    const __nv_bfloat16* __restrict__ Wh, const __nv_bfloat16* __restrict__ Wl,
    const float* __restrict__ bias, float* __restrict__ Cf)
{
    extern __shared__ __align__(16) char smraw[];
    gemm_body<0>(A, Wh, Wl, bias, Cf, nullptr, blockIdx.x * 128, smraw);
}

// ---------------------------------------------------------------------------
// LN + exact GELU block helper
// ---------------------------------------------------------------------------
__device__ __forceinline__ float ln_gelu_block(
    float a, const float* __restrict__ g, const float* __restrict__ bln,
    float* red, int c)
{
    float s1 = a, s2 = a * a;
#pragma unroll
    for (int o = 16; o > 0; o >>= 1) {
        s1 += __shfl_xor_sync(0xffffffffu, s1, o);
        s2 += __shfl_xor_sync(0xffffffffu, s2, o);
    }
    if ((c & 31) == 0) { red[c >> 5] = s1; red[8 + (c >> 5)] = s2; }
    __syncthreads();
    if (c == 0) {
        float a0 = 0.f, b0 = 0.f;
#pragma unroll
        for (int i = 0; i < 8; i++) { a0 += red[i]; b0 += red[8 + i]; }
        red[0] = a0; red[8] = b0;
    }
    __syncthreads();
    const float mean = red[0] * (1.f / 256.f);
    const float var  = red[8] * (1.f / 256.f) - mean * mean;
    float y = (a - mean) * rsqrtf(var + 1e-5f) * g[c] + bln[c];
    y = 0.5f * y * (1.0f + erff(y * 0.70710678118654752f));
    __syncthreads();
    return y;
}

// ---------------------------------------------------------------------------
// dwconv_fused + x-pack + weight split (round-9, verified)
// ---------------------------------------------------------------------------
__global__ __launch_bounds__(512) void dwconv_wsplit(
    const float* __restrict__ x, uint32_t* __restrict__ xp,
    const float* __restrict__ w1, const float* __restrict__ b1c,
    const float* __restrict__ g1, const float* __restrict__ bl1,
    const float* __restrict__ w2, const float* __restrict__ b2c,
    const float* __restrict__ g2, const float* __restrict__ bl2,
    uint32_t* __restrict__ x1p, uint32_t* __restrict__ x2p,
    const float* __restrict__ w0m, const float* __restrict__ w1m,
    const float* __restrict__ w2m, const float* __restrict__ w3m,
    __nv_bfloat16* __restrict__ h0, __nv_bfloat16* __restrict__ l0,
    __nv_bfloat16* __restrict__ h1, __nv_bfloat16* __restrict__ l1,
    __nv_bfloat16* __restrict__ h2, __nv_bfloat16* __restrict__ l2,
    __nv_bfloat16* __restrict__ h3, __nv_bfloat16* __restrict__ l3)
{
    if (blockIdx.x >= 256) {
        const int widx = blockIdx.x - 256;
        const int which = widx >> 7;
        const int i = (widx & 127) * 512 + threadIdx.x;
        const float* in = which == 0 ? w0m : which == 1 ? w1m : which == 2 ? w2m : w3m;
        __nv_bfloat16* oh = which == 0 ? h0 : which == 1 ? h1 : which == 2 ? h2 : h3;
        __nv_bfloat16* ol = which == 0 ? l0 : which == 1 ? l1 : which == 2 ? l2 : l3;
        const float v = in[i];
        const __nv_bfloat16 hi = __float2bfloat16(v);
        oh[i] = hi;
        ol[i] = __float2bfloat16(v - __bfloat162float(hi));
        return;
    }

    extern __shared__ float sw[];
    float* w2s = sw;
    float* w1s = sw + 64 * 257;
    float* redb = sw + 80 * 257;

    const int tid = threadIdx.x;
    const int c = tid & 255;
    const int win = tid >> 8;
    float* red = redb + win * 16;

    const int b = blockIdx.x >> 5;
    const int pair = blockIdx.x & 31;
    const int t2 = pair * 2 + win;
    const int oh2 = t2 >> 3, ow2 = t2 & 7;

    for (int i = tid; i < 64 * 256; i += 512)
        w2s[(i & 63) * 257 + (i >> 6)] = w2[i];
    for (int i = tid; i < 16 * 256; i += 512)
        w1s[(i & 15) * 257 + (i >> 4)] = w1[i];
    __syncthreads();

    float acc2 = b2c[c];
    float acc1[2][2];
    acc1[0][0] = acc1[0][1] = acc1[1][0] = acc1[1][1] = b1c[c];

#pragma unroll
    for (int kh = 0; kh < 8; kh++) {
#pragma unroll
        for (int kw = 0; kw < 8; kw++) {
            const int ih = oh2 * 8 + kh, iw = ow2 * 8 + kw;
            const size_t xi = ((size_t)b * NTOK + ih * 64 + iw) * CH + c;
            const float xv = x[xi];
            xp[xi] = pack_hilo(xv);
            acc2 += xv * w2s[(kh * 8 + kw) * 257 + c];
            acc1[kh >> 2][kw >> 2] += xv * w1s[((kh & 3) * 4 + (kw & 3)) * 257 + c];
        }
    }

    const float y2 = ln_gelu_block(acc2, g2, bl2, red, c);
    x2p[((size_t)b * 64 + t2) * CH + c] = pack_hilo(y2);
#pragma unroll
    for (int i = 0; i < 2; i++)
#pragma unroll
        for (int j = 0; j < 2; j++) {
            const float y1 = ln_gelu_block(acc1[i][j], g1, bl1, red, c);
            const int t1 = (oh2 * 2 + i) * 16 + (ow2 * 2 + j);
            x1p[((size_t)b * 256 + t1) * CH + c] = pack_hilo(y1);
        }
}

// ---------------------------------------------------------------------------
// Fused v local conv (+residual) -> packed V^T [b,h][e][s]
// ---------------------------------------------------------------------------
__global__ __launch_bounds__(128) void vconv_fused(
    const float* __restrict__ kv1, const float* __restrict__ lcw1,
    const float* __restrict__ lcb1, uint32_t* __restrict__ v1p,
    const float* __restrict__ kv2, const float* __restrict__ lcw2,
    const float* __restrict__ lcb2, uint32_t* __restrict__ v2p)
{
    int token, HS;
    const float *kv, *lcw, *lcb;
    uint32_t* vtp;
    if (blockIdx.x < BATCH * 256) {
        token = blockIdx.x; HS = 16; kv = kv1; lcw = lcw1; lcb = lcb1; vtp = v1p;
    } else {
        token = blockIdx.x - BATCH * 256; HS = 8; kv = kv2; lcw = lcw2; lcb = lcb2; vtp = v2p;
    }
    const int NS = HS * HS;
    const int b  = token / NS;
    const int s  = token - b * NS;
    const int hs = s / HS, ws = s - hs * HS;
    const int c  = threadIdx.x;

    float acc = lcb[c];
#pragma unroll
    for (int kh = 0; kh < 3; kh++)
#pragma unroll
        for (int kw = 0; kw < 3; kw++) {
            const int ih = hs - 1 + kh, iw = ws - 1 + kw;
            if (ih >= 0 && ih < HS && iw >= 0 && iw < HS)
                acc += kv[((size_t)b * NS + ih * HS + iw) * 256 + 128 + c]
                     * lcw[c * 9 + kh * 3 + kw];
        }
    const float v = kv[(size_t)token * 256 + 128 + c] + acc;
    const int h = c >> 5, e = c & 31;
    vtp[(((size_t)b * 4 + h) * 32 + e) * NS + s] = pack_hilo(v);
}

// ---------------------------------------------------------------------------
// Flash attention: q/k as plain bf16 (hi-only), V packed.
// 64 q / 256 threads / 2 blocks per SM. Phase-1: direct LDS.32, no PRMT.
// ---------------------------------------------------------------------------
template<int NS>
__device__ __forceinline__ void attn_body(
    const __nv_bfloat16* __restrict__ qh,
    const __nv_bfloat16* __restrict__ kh,
    const uint32_t* __restrict__ vtp,
    uint32_t* __restrict__ catp,
    int qoff, int ooff, int bh, char* smc)
{
    constexpr int SCH = NS / 4;
    constexpr int NT2 = SCH / 8;
    constexpr int KT  = SCH / 16;
    constexpr int LDB = 40;            // bf16 row stride Q/K
    constexpr int VSP = NS + 4;        // u32 row stride V
    constexpr int CHK = NS / 4;        // 16B chunks per V row
    // byte offsets
    constexpr int OFF_KS_B = 64 * LDB * 2;                 // 5120
    constexpr int OFF_VS_B = OFF_KS_B + NS * LDB * 2;
    constexpr int OFF_PB_B = OFF_VS_B + 32 * VSP * 4;
    constexpr int OFF_ST_B = OFF_PB_B + 8 * 32 * 34 * 4;
    const float kfac = 0.17677669529663689f * 1.4426950408889634f;

    __nv_bfloat16* Qs = (__nv_bfloat16*)smc;               // [64][LDB]
    __nv_bfloat16* Ks = (__nv_bfloat16*)(smc + OFF_KS_B);  // [NS][LDB]
    uint32_t*      Vs = (uint32_t*)(smc + OFF_VS_B);       // [32][VSP]
    float*         pb = (float*)(smc + OFF_PB_B);          // [8][32][34]
    float*         mx = (float*)(smc + OFF_ST_B);          // [4][64]
    float*        smr = mx + 256;                          // [4][64]

    const int b = bh >> 2, h = bh & 3;
    const int q0 = blockIdx.y * 64;
    const int tid = threadIdx.x, lane = tid & 31, w = tid >> 5;
    const int g = lane >> 2, qk = (lane & 3) * 2;
    const int wm = w >> 2, wn = w & 3;

    // async staging: Q+K bf16 (group 0), V packed (group 1)
    {
        const int r = tid >> 2, cw = tid & 3;   // 64 rows x 4 chunks
        cpa16(&Qs[r * LDB + cw * 8],
              &qh[((size_t)(b * 4096 + q0 + r)) * 256 + qoff + h * 32 + cw * 8]);
    }
    for (int c = tid; c < NS * 4; c += 256) {
        const int s = c >> 2, cw = c & 3;
        cpa16(&Ks[s * LDB + cw * 8],
              &kh[((size_t)(b * NS + s)) * 128 + h * 32 + cw * 8]);
    }
    asm volatile("cp.async.commit_group;\n" ::: "memory");
    for (int c = tid; c < 32 * CHK; c += 256) {
        const int e = c / CHK, s4 = c % CHK;
        cpa16(&Vs[e * VSP + s4 * 4],
              &vtp[(((size_t)(b * 4 + h)) * 32 + e) * NS + s4 * 4]);
    }
    asm volatile("cp.async.commit_group;\n" ::: "memory");
    asm volatile("cp.async.wait_group 1;\n" ::: "memory");
    __syncthreads();

    // phase 1: S = Q K^T (hi-only, direct LDS.32)
    float acc[2][NT2][4];
#pragma unroll
    for (int mt = 0; mt < 2; mt++)
#pragma unroll
        for (int nt = 0; nt < NT2; nt++)
#pragma unroll
            for (int r = 0; r < 4; r++) acc[mt][nt][r] = 0.f;

#pragma unroll
    for (int kc = 0; kc < 2; kc++) {
        const int kb = kc * 16;
        uint32_t ah[2][4];
#pragma unroll
        for (int mt = 0; mt < 2; mt++) {
            const int row = wm * 32 + mt * 16 + g;
            const int o0 = row * LDB + kb + qk;
            ah[mt][0] = *(const uint32_t*)&Qs[o0];
            ah[mt][1] = *(const uint32_t*)&Qs[o0 + 8 * LDB];
            ah[mt][2] = *(const uint32_t*)&Qs[o0 + 8];
            ah[mt][3] = *(const uint32_t*)&Qs[o0 + 8 * LDB + 8];
        }
#pragma unroll
        for (int nt = 0; nt < NT2; nt++) {
            const int srow = wn * SCH + nt * 8 + g;
            const int o0 = srow * LDB + kb + qk;
            uint32_t bh2[2];
            bh2[0] = *(const uint32_t*)&Ks[o0];
            bh2[1] = *(const uint32_t*)&Ks[o0 + 8];
#pragma unroll
            for (int mt = 0; mt < 2; mt++)
                mma16816(acc[mt][nt], ah[mt], bh2);
        }
    }

    // chunk max
#pragma unroll
    for (int mt = 0; mt < 2; mt++)
#pragma unroll
        for (int half = 0; half < 2; half++) {
            float m = acc[mt][0][half * 2];
#pragma unroll
            for (int nt = 0; nt < NT2; nt++) {
                m = fmaxf(m, acc[mt][nt][half * 2]);
                m = fmaxf(m, acc[mt][nt][half * 2 + 1]);
            }
            m = fmaxf(m, __shfl_xor_sync(0xffffffffu, m, 1));
            m = fmaxf(m, __shfl_xor_sync(0xffffffffu, m, 2));
            if ((lane & 3) == 0)
                mx[wn * 64 + wm * 32 + mt * 16 + half * 8 + g] = m;
        }
    __syncthreads();   // barrier 1

    // global max, exp, chunk sums
#pragma unroll
    for (int mt = 0; mt < 2; mt++)
#pragma unroll
        for (int half = 0; half < 2; half++) {
            const int row = wm * 32 + mt * 16 + half * 8 + g;
            float m = fmaxf(fmaxf(mx[row], mx[64 + row]),
                            fmaxf(mx[128 + row], mx[192 + row]));
            float s = 0.f;
#pragma unroll
            for (int nt = 0; nt < NT2; nt++) {
                float e0 = exp2f((acc[mt][nt][half * 2]     - m) * kfac);
                float e1 = exp2f((acc[mt][nt][half * 2 + 1] - m) * kfac);
                acc[mt][nt][half * 2]     = e0;
                acc[mt][nt][half * 2 + 1] = e1;
                s += e0 + e1;
            }
            s += __shfl_xor_sync(0xffffffffu, s, 1);
            s += __shfl_xor_sync(0xffffffffu, s, 2);
            if ((lane & 3) == 0) smr[wn * 64 + row] = s;
        }
    asm volatile("cp.async.wait_group 0;\n" ::: "memory");
    __syncthreads();   // barrier 2

    // phase 3: O_partial = P V (full 3-term)
    float acc3[2][4][4];
#pragma unroll
    for (int mt = 0; mt < 2; mt++)
#pragma unroll
        for (int nt = 0; nt < 4; nt++)
#pragma unroll
            for (int r = 0; r < 4; r++) acc3[mt][nt][r] = 0.f;

#pragma unroll
    for (int kt = 0; kt < KT; kt++) {
        uint32_t bh3[4][2], bl3[4][2];
#pragma unroll
        for (int nt3 = 0; nt3 < 4; nt3++) {
            const int e = nt3 * 8 + g;
            const int base = e * VSP + wn * SCH + kt * 16 + qk;
            uint2 p0 = *(const uint2*)&Vs[base];
            uint2 p1 = *(const uint2*)&Vs[base + 8];
            bh3[nt3][0] = __byte_perm(p0.x, p0.y, 0x5410);
            bl3[nt3][0] = __byte_perm(p0.x, p0.y, 0x7632);
            bh3[nt3][1] = __byte_perm(p1.x, p1.y, 0x5410);
            bl3[nt3][1] = __byte_perm(p1.x, p1.y, 0x7632);
        }
#pragma unroll
        for (int mt = 0; mt < 2; mt++) {
            uint32_t ah[4], al[4];
            pack2_hilo(acc[mt][2 * kt][0],     acc[mt][2 * kt][1],     ah[0], al[0]);
            pack2_hilo(acc[mt][2 * kt][2],     acc[mt][2 * kt][3],     ah[1], al[1]);
            pack2_hilo(acc[mt][2 * kt + 1][0], acc[mt][2 * kt + 1][1], ah[2], al[2]);
            pack2_hilo(acc[mt][2 * kt + 1][2], acc[mt][2 * kt + 1][3], ah[3], al[3]);
#pragma unroll
            for (int nt3 = 0; nt3 < 4; nt3++) {
                mma16816(acc3[mt][nt3], ah, bh3[nt3]);
                mma16816(acc3[mt][nt3], al, bh3[nt3]);
                mma16816(acc3[mt][nt3], ah, bl3[nt3]);
            }
        }
    }

    // write partials (slot = wn*2 + wm)
#pragma unroll
    for (int mt = 0; mt < 2; mt++)
#pragma unroll
        for (int nt3 = 0; nt3 < 4; nt3++) {
            const int rl = mt * 16 + g;
            const int base = ((wn * 2 + wm) * 32 + rl) * 34 + nt3 * 8 + qk;
            *(float2*)&pb[base] = make_float2(acc3[mt][nt3][0], acc3[mt][nt3][1]);
            *(float2*)&pb[base + 8 * 34] = make_float2(acc3[mt][nt3][2], acc3[mt][nt3][3]);
        }
    __syncthreads();   // barrier 3

    // reduction + epilogue
#pragma unroll
    for (int rr = 0; rr < 4; rr++) {
        const int rloc = rr * 8 + (lane >> 2);
        const int row = wm * 32 + rloc;
        const int cl = wn * 8 + (lane & 3) * 2;
        float ox = 0.f, oy = 0.f;
#pragma unroll
        for (int wv = 0; wv < 4; wv++) {
            float2 p = *(const float2*)&pb[((wv * 2 + wm) * 32 + rloc) * 34 + cl];
            ox += p.x; oy += p.y;
        }
        const float inv = 1.0f / (smr[row] + smr[64 + row] +
                                  smr[128 + row] + smr[192 + row]);
        const int col = ooff + h * 32 + cl;
        *(uint2*)&catp[((size_t)(b * 4096 + q0 + row)) * 256 + col] =
            make_uint2(pack_hilo(ox * inv), pack_hilo(oy * inv));
    }
}

__global__ __launch_bounds__(256, 2) void attn_b1(
    const __nv_bfloat16* __restrict__ qh, const __nv_bfloat16* __restrict__ kh,
    const uint32_t* __restrict__ vtp, uint32_t* __restrict__ catp)
{
    extern __shared__ char smc[];
    attn_body<256>(qh, kh, vtp, catp, 0, 0, blockIdx.x, smc);
}

__global__ __launch_bounds__(256, 2) void attn_b2(
    const __nv_bfloat16* __restrict__ qh, const __nv_bfloat16* __restrict__ kh,
    const uint32_t* __restrict__ vtp, uint32_t* __restrict__ catp)
{
    extern __shared__ char smc[];
    attn_body<64>(qh, kh, vtp, catp, 128, 128, blockIdx.x, smc);
}

// ---------------------------------------------------------------------------
// launch
// ---------------------------------------------------------------------------
extern "C" void kernel_launch(void* const* d_in, const int* in_sizes, int n_in,
                              void* d_out, int out_size)
{
    const float* x      = (const float*)d_in[0];
    const float* q_w    = (const float*)d_in[1];
    const float* kv1_w  = (const float*)d_in[2];
    const float* kv2_w  = (const float*)d_in[3];
    const float* proj_w = (const float*)d_in[4];
    const float* proj_b = (const float*)d_in[5];
    const float* sr1_w  = (const float*)d_in[6];
    const float* sr1_b  = (const float*)d_in[7];
    const float* sr2_w  = (const float*)d_in[8];
    const float* sr2_b  = (const float*)d_in[9];
    const float* ln1_g  = (const float*)d_in[10];
    const float* ln1_b  = (const float*)d_in[11];
    const float* ln2_g  = (const float*)d_in[12];
    const float* ln2_b  = (const float*)d_in[13];
    const float* lc1_w  = (const float*)d_in[14];
    const float* lc1_b  = (const float*)d_in[15];
    const float* lc2_w  = (const float*)d_in[16];
    const float* lc2_b  = (const float*)d_in[17];
    float* out = (float*)d_out;

    uint32_t *p_xp, *p_catp, *p_x1p, *p_x2p, *p_v1p, *p_v2p;
    float *p_kv1, *p_kv2;
    __nv_bfloat16 *p_qh, *p_k1h, *p_k2h;
    __nv_bfloat16 *p_qwh, *p_qwl, *p_k1wh, *p_k1wl, *p_k2wh, *p_k2wl, *p_pwh, *p_pwl;
    cudaGetSymbolAddress((void**)&p_xp,   g_xp);
    cudaGetSymbolAddress((void**)&p_qh,   g_qh);
    cudaGetSymbolAddress((void**)&p_catp, g_catp);
    cudaGetSymbolAddress((void**)&p_x1p,  g_x1p);
    cudaGetSymbolAddress((void**)&p_x2p,  g_x2p);
    cudaGetSymbolAddress((void**)&p_kv1,  g_kv1);
    cudaGetSymbolAddress((void**)&p_kv2,  g_kv2);
    cudaGetSymbolAddress((void**)&p_k1h,  g_k1h);
    cudaGetSymbolAddress((void**)&p_k2h,  g_k2h);
    cudaGetSymbolAddress((void**)&p_v1p,  g_v1p);
    cudaGetSymbolAddress((void**)&p_v2p,  g_v2p);
    cudaGetSymbolAddress((void**)&p_qwh,  g_qwh);
    cudaGetSymbolAddress((void**)&p_qwl,  g_qwl);
    cudaGetSymbolAddress((void**)&p_k1wh, g_k1wh);
    cudaGetSymbolAddress((void**)&p_k1wl, g_k1wl);
    cudaGetSymbolAddress((void**)&p_k2wh, g_k2wh);
    cudaGetSymbolAddress((void**)&p_k2wl, g_k2wl);
    cudaGetSymbolAddress((void**)&p_pwh,  g_pwh);
    cudaGetSymbolAddress((void**)&p_pwl,  g_pwl);

    const int smem_gemm = 3 * (128 * 40 * 4) + 2 * (3 * 256 * 40 * 2);  // 184,320
    const int smem_dw   = 80 * 257 * 4 + 128;
    // attn smem bytes: Q(5120) + K(NS*80) + V(32*(NS+4)*4) + pb(34816) + stats(2048)
    const int smem_a1 = 5120 + 256 * 80 + 32 * 260 * 4 + 34816 + 2048;  // 95,744
    const int smem_a2 = 5120 + 64 * 80 + 32 * 68 * 4 + 34816 + 2048;    // 55,808
    cudaFuncSetAttribute(gemm_all,  cudaFuncAttributeMaxDynamicSharedMemorySize, smem_gemm);
    cudaFuncSetAttribute(gemm_proj, cudaFuncAttributeMaxDynamicSharedMemorySize, smem_gemm);
    cudaFuncSetAttribute(dwconv_wsplit, cudaFuncAttributeMaxDynamicSharedMemorySize, smem_dw);
    cudaFuncSetAttribute(attn_b1, cudaFuncAttributeMaxDynamicSharedMemorySize, smem_a1);
    cudaFuncSetAttribute(attn_b2, cudaFuncAttributeMaxDynamicSharedMemorySize, smem_a2);

    // 0: dwconv (+x pack) + weight split
    dwconv_wsplit<<<768, 512, smem_dw>>>(
        x, p_xp, sr1_w, sr1_b, ln1_g, ln1_b, sr2_w, sr2_b, ln2_g, ln2_b,
        p_x1p, p_x2p,
        q_w, kv1_w, kv2_w, proj_w,
        p_qwh, p_qwl, p_k1wh, p_k1wl, p_k2wh, p_k2wl, p_pwh, p_pwl);
    // 1: all projections (q 256 + kv1 16 + kv2 4 blocks)
    gemm_all<<<276, 512, smem_gemm>>>(
        p_xp, p_x1p, p_x2p, p_qwh, p_qwl, p_k1wh, p_k1wl, p_k2wh, p_k2wl,
        p_qh, p_kv1, p_k1h, p_kv2, p_k2h);
    // 2: v local conv -> packed V^T
    vconv_fused<<<BATCH * 256 + BATCH * 64, 128>>>(
        p_kv1, lc1_w, lc1_b, p_v1p, p_kv2, lc2_w, lc2_b, p_v2p);
    // 3: attention branch 1 (PROFILED SLOT)
    attn_b1<<<dim3(32, 64), 256, smem_a1>>>(p_qh, p_k1h, p_v1p, p_catp);
    // 4: attention branch 2
    attn_b2<<<dim3(32, 64), 256, smem_a2>>>(p_qh, p_k2h, p_v2p, p_catp);
    // 5: output projection
    gemm_proj<<<256, 512, smem_gemm>>>(p_catp, p_pwh, p_pwl, proj_b, out);
}

// round 16
// speedup vs baseline: 1.2161x; 1.0201x over previous
#include <cuda_runtime.h>
#include <cuda_bf16.h>
#include <cstdint>

// Problem constants: B=8, H=W=64, N=4096, C=256, nh=8, nh2=4, hd=32, sr=8
#define BATCH 8
#define NTOK 4096
#define CH 256

// ---------------------------------------------------------------------------
// Scratch (device globals)
// ---------------------------------------------------------------------------
__device__ __nv_bfloat16 g_xh  [(size_t)BATCH * NTOK * CH];   // x HI only (q-gemm A)
__device__ __nv_bfloat16 g_qh  [(size_t)BATCH * NTOK * CH];   // q HI only
__device__ uint32_t      g_catp[(size_t)BATCH * NTOK * CH];   // cat packed (hi,lo)
__device__ uint32_t      g_x1p [BATCH * 256 * CH];
__device__ uint32_t      g_x2p [BATCH * 64 * CH];
__device__ float         g_kv1 [BATCH * 256 * CH];
__device__ float         g_kv2 [BATCH * 64 * CH];
__device__ __nv_bfloat16 g_k1h [BATCH * 256 * 128];           // k HI only
__device__ __nv_bfloat16 g_k2h [BATCH * 64 * 128];
__device__ __nv_bfloat16 g_v1h [BATCH * 4 * 32 * 256], g_v1l [BATCH * 4 * 32 * 256];
__device__ __nv_bfloat16 g_v2h [BATCH * 4 * 32 * 64],  g_v2l [BATCH * 4 * 32 * 64];
// weight splits (hi/lo planes)
__device__ __nv_bfloat16 g_qwh [256 * 256], g_qwl [256 * 256];
__device__ __nv_bfloat16 g_k1wh[256 * 256], g_k1wl[256 * 256];
__device__ __nv_bfloat16 g_k2wh[256 * 256], g_k2wl[256 * 256];
__device__ __nv_bfloat16 g_pwh [256 * 256], g_pwl [256 * 256];

// ---------------------------------------------------------------------------
// helpers
// ---------------------------------------------------------------------------
__device__ __forceinline__ uint32_t pack_hilo(float v) {
    __nv_bfloat16 h = __float2bfloat16(v);
    __nv_bfloat16 l = __float2bfloat16(v - __bfloat162float(h));
    return (uint32_t)__bfloat16_as_ushort(h) |
           ((uint32_t)__bfloat16_as_ushort(l) << 16);
}

__device__ __forceinline__ uint32_t pack_hi2(float p0, float p1) {
    uint32_t hp;
    asm("cvt.rn.bf16x2.f32 %0, %1, %2;" : "=r"(hp) : "f"(p1), "f"(p0));
    return hp;
}

__device__ __forceinline__ void pack2_hilo(
    float p0, float p1, uint32_t& h, uint32_t& l)
{
    uint32_t hp;
    asm("cvt.rn.bf16x2.f32 %0, %1, %2;" : "=r"(hp) : "f"(p1), "f"(p0));
    const float r0 = p0 - __uint_as_float(hp << 16);
    const float r1 = p1 - __uint_as_float(hp & 0xffff0000u);
    uint32_t lp;
    asm("cvt.rn.bf16x2.f32 %0, %1, %2;" : "=r"(lp) : "f"(r1), "f"(r0));
    h = hp; l = lp;
}

__device__ __forceinline__ void mma16816(
    float* c, const uint32_t* a, const uint32_t* b)
{
    asm volatile(
        "mma.sync.aligned.m16n8k16.row.col.f32.bf16.bf16.f32 "
        "{%0,%1,%2,%3}, {%4,%5,%6,%7}, {%8,%9}, {%0,%1,%2,%3};"
        : "+f"(c[0]), "+f"(c[1]), "+f"(c[2]), "+f"(c[3])
        : "r"(a[0]), "r"(a[1]), "r"(a[2]), "r"(a[3]), "r"(b[0]), "r"(b[1]));
}

__device__ __forceinline__ void cpa16(void* dst, const void* src) {
    uint32_t d = (uint32_t)__cvta_generic_to_shared(dst);
    asm volatile("cp.async.cg.shared.global [%0], [%1], 16;\n"
                 :: "r"(d), "l"(src));
}

// ---------------------------------------------------------------------------
// q-GEMM body: 1-term hi-only. A bf16 [M,256], W hi bf16 [256,256].
// 512 threads, 128x256 tile, 3-stage cp.async. 16 warps = 4m x 4n.
// ---------------------------------------------------------------------------
__device__ __forceinline__ void gemm_q_body(
    const __nv_bfloat16* __restrict__ Ag,
    const __nv_bfloat16* __restrict__ Wh,
    __nv_bfloat16* __restrict__ Cb,
    int m0, char* smraw)
{
    constexpr int LD  = 40;
    constexpr int ASZ = 128 * LD;
    constexpr int BSZ = 256 * LD;
    __nv_bfloat16* Ah = (__nv_bfloat16*)smraw;   // [3][128][LD]
    __nv_bfloat16* Bh = Ah + 3 * ASZ;            // [3][256][LD]

    const int tid = threadIdx.x;
    const int w = tid >> 5, lane = tid & 31;
    const int wm = w & 3, wn = w >> 2;
    const int g = lane >> 2, qk = (lane & 3) * 2;

    auto load_stage = [&](int s, int k0) {
        {
            const int row = tid >> 2, ch = tid & 3;
            cpa16(&Ah[s * ASZ + row * LD + ch * 8],
                  &Ag[(size_t)(m0 + row) * 256 + k0 + ch * 8]);
        }
#pragma unroll
        for (int i = 0; i < 2; i++) {
            const int c = tid + i * 512;
            const int row = c >> 2, ch = c & 3;
            cpa16(&Bh[s * BSZ + row * LD + ch * 8],
                  &Wh[(size_t)row * 256 + k0 + ch * 8]);
        }
        asm volatile("cp.async.commit_group;\n" ::: "memory");
    };

    float acc[2][8][4];
#pragma unroll
    for (int mt = 0; mt < 2; mt++)
#pragma unroll
        for (int nt = 0; nt < 8; nt++)
#pragma unroll
            for (int r = 0; r < 4; r++) acc[mt][nt][r] = 0.f;

    load_stage(0, 0);
    load_stage(1, 32);

    for (int it = 0; it < 8; it++) {
        if (it < 7) asm volatile("cp.async.wait_group 1;\n" ::: "memory");
        else        asm volatile("cp.async.wait_group 0;\n" ::: "memory");
        __syncthreads();
        if (it + 2 < 8) load_stage((it + 2) % 3, (it + 2) * 32);

        const int s = it % 3;
        const __nv_bfloat16* Ahs = Ah + s * ASZ;
        const __nv_bfloat16* Bhs = Bh + s * BSZ;

#pragma unroll
        for (int ks = 0; ks < 2; ks++) {
            const int kb = ks * 16;
            uint32_t ah[2][4];
#pragma unroll
            for (int mt = 0; mt < 2; mt++) {
                const int row = wm * 32 + mt * 16 + g;
                const int o0 = row * LD + kb + qk;
                ah[mt][0] = *(const uint32_t*)&Ahs[o0];
                ah[mt][1] = *(const uint32_t*)&Ahs[o0 + 8 * LD];
                ah[mt][2] = *(const uint32_t*)&Ahs[o0 + 8];
                ah[mt][3] = *(const uint32_t*)&Ahs[o0 + 8 * LD + 8];
            }
#pragma unroll
            for (int nt = 0; nt < 8; nt++) {
                const __nv_bfloat16* pb = &Bhs[(wn * 64 + nt * 8 + g) * LD + kb + qk];
                uint32_t bf[2];
                bf[0] = *(const uint32_t*)pb;
                bf[1] = *(const uint32_t*)(pb + 8);
#pragma unroll
                for (int mt = 0; mt < 2; mt++)
                    mma16816(acc[mt][nt], ah[mt], bf);
            }
        }
        __syncthreads();
    }

#pragma unroll
    for (int mt = 0; mt < 2; mt++) {
        const int r = m0 + wm * 32 + mt * 16 + g;
#pragma unroll
        for (int nt = 0; nt < 8; nt++) {
            const int col = wn * 64 + nt * 8 + qk;
            *(uint32_t*)&Cb[(size_t)r * 256 + col] =
                pack_hi2(acc[mt][nt][0], acc[mt][nt][1]);
            *(uint32_t*)&Cb[(size_t)(r + 8) * 256 + col] =
                pack_hi2(acc[mt][nt][2], acc[mt][nt][3]);
        }
    }
}

// ---------------------------------------------------------------------------
// Full GEMM body (3-term, A packed u32): MODE 0 fp32+bias, MODE 2 fp32+k-hi.
// ---------------------------------------------------------------------------
template<int MODE>
__device__ __forceinline__ void gemm_body(
    const uint32_t* __restrict__ A,
    const __nv_bfloat16* __restrict__ Wh,
    const __nv_bfloat16* __restrict__ Wl,
    const float* __restrict__ bias,
    float* __restrict__ Cf, __nv_bfloat16* __restrict__ Cb,
    int m0, char* smraw)
{
    constexpr int LDA = 40;
    constexpr int LDB = 40;
    constexpr int ASZ = 128 * LDA;
    constexpr int BSZ = 256 * LDB;

    uint32_t*      Ap = (uint32_t*)smraw;
    __nv_bfloat16* Bh = (__nv_bfloat16*)(Ap + 3 * ASZ);
    __nv_bfloat16* Bl = Bh + 3 * BSZ;

    const int tid = threadIdx.x;
    const int w = tid >> 5, lane = tid & 31;
    const int wm = w & 3, wn = w >> 2;
    const int g = lane >> 2, qk = (lane & 3) * 2;

    auto load_stage = [&](int s, int k0) {
#pragma unroll
        for (int i = 0; i < 2; i++) {
            const int c = tid + i * 512;
            const int row = c >> 3, ch = c & 7;
            cpa16(&Ap[s * ASZ + row * LDA + ch * 4],
                  &A[(size_t)(m0 + row) * 256 + k0 + ch * 4]);
        }
#pragma unroll
        for (int i = 0; i < 2; i++) {
            const int c = tid + i * 512;
            const int row = c >> 2, ch = c & 3;
            cpa16(&Bh[s * BSZ + row * LDB + ch * 8],
                  &Wh[(size_t)row * 256 + k0 + ch * 8]);
        }
#pragma unroll
        for (int i = 0; i < 2; i++) {
            const int c = tid + i * 512;
            const int row = c >> 2, ch = c & 3;
            cpa16(&Bl[s * BSZ + row * LDB + ch * 8],
                  &Wl[(size_t)row * 256 + k0 + ch * 8]);
        }
        asm volatile("cp.async.commit_group;\n" ::: "memory");
    };

    float acc[2][8][4];
#pragma unroll
    for (int mt = 0; mt < 2; mt++)
#pragma unroll
        for (int nt = 0; nt < 8; nt++)
#pragma unroll
            for (int r = 0; r < 4; r++) acc[mt][nt][r] = 0.f;

    load_stage(0, 0);
    load_stage(1, 32);

    for (int it = 0; it < 8; it++) {
        if (it < 7) asm volatile("cp.async.wait_group 1;\n" ::: "memory");
        else        asm volatile("cp.async.wait_group 0;\n" ::: "memory");
        __syncthreads();
        if (it + 2 < 8) load_stage((it + 2) % 3, (it + 2) * 32);

        const int s = it % 3;
        const uint32_t*      As  = Ap + s * ASZ;
        const __nv_bfloat16* Bhs = Bh + s * BSZ;
        const __nv_bfloat16* Bls = Bl + s * BSZ;

#pragma unroll
        for (int ks = 0; ks < 2; ks++) {
            const int kb = ks * 16;
            uint32_t ah[2][4], al[2][4];
#pragma unroll
            for (int mt = 0; mt < 2; mt++) {
                const int row = wm * 32 + mt * 16 + g;
                uint2 p0 = *(const uint2*)&As[row * LDA + kb + qk];
                uint2 p1 = *(const uint2*)&As[(row + 8) * LDA + kb + qk];
                uint2 p2 = *(const uint2*)&As[row * LDA + kb + qk + 8];
                uint2 p3 = *(const uint2*)&As[(row + 8) * LDA + kb + qk + 8];
                ah[mt][0] = __byte_perm(p0.x, p0.y, 0x5410);
                al[mt][0] = __byte_perm(p0.x, p0.y, 0x7632);
                ah[mt][1] = __byte_perm(p1.x, p1.y, 0x5410);
                al[mt][1] = __byte_perm(p1.x, p1.y, 0x7632);
                ah[mt][2] = __byte_perm(p2.x, p2.y, 0x5410);
                al[mt][2] = __byte_perm(p2.x, p2.y, 0x7632);
                ah[mt][3] = __byte_perm(p3.x, p3.y, 0x5410);
                al[mt][3] = __byte_perm(p3.x, p3.y, 0x7632);
            }
            uint32_t bf[8][2];
#pragma unroll
            for (int nt = 0; nt < 8; nt++) {
                const __nv_bfloat16* pb = &Bhs[(wn * 64 + nt * 8 + g) * LDB + kb + qk];
                bf[nt][0] = *(const uint32_t*)pb;
                bf[nt][1] = *(const uint32_t*)(pb + 8);
            }
#pragma unroll
            for (int mt = 0; mt < 2; mt++)
#pragma unroll
                for (int nt = 0; nt < 8; nt++) {
                    mma16816(acc[mt][nt], ah[mt], bf[nt]);
                    mma16816(acc[mt][nt], al[mt], bf[nt]);
                }
#pragma unroll
            for (int nt = 0; nt < 8; nt++) {
                const __nv_bfloat16* pb = &Bls[(wn * 64 + nt * 8 + g) * LDB + kb + qk];
                bf[nt][0] = *(const uint32_t*)pb;
                bf[nt][1] = *(const uint32_t*)(pb + 8);
            }
#pragma unroll
            for (int mt = 0; mt < 2; mt++)
#pragma unroll
                for (int nt = 0; nt < 8; nt++)
                    mma16816(acc[mt][nt], ah[mt], bf[nt]);
        }
        __syncthreads();
    }

#pragma unroll
    for (int mt = 0; mt < 2; mt++) {
        const int r = m0 + wm * 32 + mt * 16 + g;
#pragma unroll
        for (int nt = 0; nt < 8; nt++) {
            const int col = wn * 64 + nt * 8 + qk;
            if constexpr (MODE == 0) {
                const float b0 = bias[col], b1 = bias[col + 1];
                *(float2*)&Cf[(size_t)r * 256 + col] =
                    make_float2(acc[mt][nt][0] + b0, acc[mt][nt][1] + b1);
                *(float2*)&Cf[(size_t)(r + 8) * 256 + col] =
                    make_float2(acc[mt][nt][2] + b0, acc[mt][nt][3] + b1);
            } else {
                *(float2*)&Cf[(size_t)r * 256 + col] =
                    make_float2(acc[mt][nt][0], acc[mt][nt][1]);
                *(float2*)&Cf[(size_t)(r + 8) * 256 + col] =
                    make_float2(acc[mt][nt][2], acc[mt][nt][3]);
                if (col < 128) {
                    *(uint32_t*)&Cb[(size_t)r * 128 + col] =
                        pack_hi2(acc[mt][nt][0], acc[mt][nt][1]);
                    *(uint32_t*)&Cb[(size_t)(r + 8) * 128 + col] =
                        pack_hi2(acc[mt][nt][2], acc[mt][nt][3]);
                }
            }
        }
    }
}

// Combined projection GEMMs: q (256 blocks, 1-term) + kv1 (16) + kv2 (4).
__global__ __launch_bounds__(512) void gemm_all(
    const __nv_bfloat16* __restrict__ xh,
    const uint32_t* __restrict__ x1p, const uint32_t* __restrict__ x2p,
    const __nv_bfloat16* __restrict__ qwh,
    const __nv_bfloat16* __restrict__ k1wh, const __nv_bfloat16* __restrict__ k1wl,
    const __nv_bfloat16* __restrict__ k2wh, const __nv_bfloat16* __restrict__ k2wl,
    __nv_bfloat16* __restrict__ qh,
    float* __restrict__ kv1, __nv_bfloat16* __restrict__ k1h,
    float* __restrict__ kv2, __nv_bfloat16* __restrict__ k2h)
{
    extern __shared__ __align__(16) char smraw[];
    if (blockIdx.x < 256)
        gemm_q_body(xh, qwh, qh, blockIdx.x * 128, smraw);
    else if (blockIdx.x < 272)
        gemm_body<2>(x1p, k1wh, k1wl, nullptr, kv1, k1h, (blockIdx.x - 256) * 128, smraw);
    else
        gemm_body<2>(x2p, k2wh, k2wl, nullptr, kv2, k2h, (blockIdx.x - 272) * 128, smraw);
}

// Output projection.
__global__ __launch_bounds__(512) void gemm_proj(
    const uint32_t* __restrict__ A,
    const __nv_bfloat16* __restrict__ Wh, const __nv_bfloat16* __restrict__ Wl,
    const float* __restrict__ bias, float* __restrict__ Cf)
{
    extern __shared__ __align__(16) char smraw[];
    gemm_body<0>(A, Wh, Wl, bias, Cf, nullptr, blockIdx.x * 128, smraw);
}

// ---------------------------------------------------------------------------
// LN + exact GELU block helper
// ---------------------------------------------------------------------------
__device__ __forceinline__ float ln_gelu_block(
    float a, const float* __restrict__ g, const float* __restrict__ bln,
    float* red, int c)
{
    float s1 = a, s2 = a * a;
#pragma unroll
    for (int o = 16; o > 0; o >>= 1) {
        s1 += __shfl_xor_sync(0xffffffffu, s1, o);
        s2 += __shfl_xor_sync(0xffffffffu, s2, o);
    }
    if ((c & 31) == 0) { red[c >> 5] = s1; red[8 + (c >> 5)] = s2; }
    __syncthreads();
    if (c == 0) {
        float a0 = 0.f, b0 = 0.f;
#pragma unroll
        for (int i = 0; i < 8; i++) { a0 += red[i]; b0 += red[8 + i]; }
        red[0] = a0; red[8] = b0;
    }
    __syncthreads();
    const float mean = red[0] * (1.f / 256.f);
    const float var  = red[8] * (1.f / 256.f) - mean * mean;
    float y = (a - mean) * rsqrtf(var + 1e-5f) * g[c] + bln[c];
    y = 0.5f * y * (1.0f + erff(y * 0.70710678118654752f));
    __syncthreads();
    return y;
}

// ---------------------------------------------------------------------------
// dwconv_fused + x-hi store + weight split
// ---------------------------------------------------------------------------
__global__ __launch_bounds__(512) void dwconv_wsplit(
    const float* __restrict__ x, __nv_bfloat16* __restrict__ xh,
    const float* __restrict__ w1, const float* __restrict__ b1c,
    const float* __restrict__ g1, const float* __restrict__ bl1,
    const float* __restrict__ w2, const float* __restrict__ b2c,
    const float* __restrict__ g2, const float* __restrict__ bl2,
    uint32_t* __restrict__ x1p, uint32_t* __restrict__ x2p,
    const float* __restrict__ w0m, const float* __restrict__ w1m,
    const float* __restrict__ w2m, const float* __restrict__ w3m,
    __nv_bfloat16* __restrict__ h0, __nv_bfloat16* __restrict__ l0,
    __nv_bfloat16* __restrict__ h1, __nv_bfloat16* __restrict__ l1,
    __nv_bfloat16* __restrict__ h2, __nv_bfloat16* __restrict__ l2,
    __nv_bfloat16* __restrict__ h3, __nv_bfloat16* __restrict__ l3)
{
    if (blockIdx.x >= 256) {
        const int widx = blockIdx.x - 256;
        const int which = widx >> 7;
        const int i = (widx & 127) * 512 + threadIdx.x;
        const float* in = which == 0 ? w0m : which == 1 ? w1m : which == 2 ? w2m : w3m;
        __nv_bfloat16* oh = which == 0 ? h0 : which == 1 ? h1 : which == 2 ? h2 : h3;
        __nv_bfloat16* ol = which == 0 ? l0 : which == 1 ? l1 : which == 2 ? l2 : l3;
        const float v = in[i];
        const __nv_bfloat16 hi = __float2bfloat16(v);
        oh[i] = hi;
        ol[i] = __float2bfloat16(v - __bfloat162float(hi));
        return;
    }

    extern __shared__ float sw[];
    float* w2s = sw;
    float* w1s = sw + 64 * 257;
    float* redb = sw + 80 * 257;

    const int tid = threadIdx.x;
    const int c = tid & 255;
    const int win = tid >> 8;
    float* red = redb + win * 16;

    const int b = blockIdx.x >> 5;
    const int pair = blockIdx.x & 31;
    const int t2 = pair * 2 + win;
    const int oh2 = t2 >> 3, ow2 = t2 & 7;

    for (int i = tid; i < 64 * 256; i += 512)
        w2s[(i & 63) * 257 + (i >> 6)] = w2[i];
    for (int i = tid; i < 16 * 256; i += 512)
        w1s[(i & 15) * 257 + (i >> 4)] = w1[i];
    __syncthreads();

    float acc2 = b2c[c];
    float acc1[2][2];
    acc1[0][0] = acc1[0][1] = acc1[1][0] = acc1[1][1] = b1c[c];

#pragma unroll
    for (int kh = 0; kh < 8; kh++) {
#pragma unroll
        for (int kw = 0; kw < 8; kw++) {
            const int ih = oh2 * 8 + kh, iw = ow2 * 8 + kw;
            const size_t xi = ((size_t)b * NTOK + ih * 64 + iw) * CH + c;
            const float xv = x[xi];
            xh[xi] = __float2bfloat16(xv);
            acc2 += xv * w2s[(kh * 8 + kw) * 257 + c];
            acc1[kh >> 2][kw >> 2] += xv * w1s[((kh & 3) * 4 + (kw & 3)) * 257 + c];
        }
    }

    const float y2 = ln_gelu_block(acc2, g2, bl2, red, c);
    x2p[((size_t)b * 64 + t2) * CH + c] = pack_hilo(y2);
#pragma unroll
    for (int i = 0; i < 2; i++)
#pragma unroll
        for (int j = 0; j < 2; j++) {
            const float y1 = ln_gelu_block(acc1[i][j], g1, bl1, red, c);
            const int t1 = (oh2 * 2 + i) * 16 + (ow2 * 2 + j);
            x1p[((size_t)b * 256 + t1) * CH + c] = pack_hilo(y1);
        }
}

// ---------------------------------------------------------------------------
// Fused v local conv (+residual) -> V^T hi/lo bf16 planes [b,h][e][s]
// ---------------------------------------------------------------------------
__global__ __launch_bounds__(128) void vconv_fused(
    const float* __restrict__ kv1, const float* __restrict__ lcw1,
    const float* __restrict__ lcb1,
    __nv_bfloat16* __restrict__ v1h, __nv_bfloat16* __restrict__ v1l,
    const float* __restrict__ kv2, const float* __restrict__ lcw2,
    const float* __restrict__ lcb2,
    __nv_bfloat16* __restrict__ v2h, __nv_bfloat16* __restrict__ v2l)
{
    int token, HS;
    const float *kv, *lcw, *lcb;
    __nv_bfloat16 *vh, *vl;
    if (blockIdx.x < BATCH * 256) {
        token = blockIdx.x; HS = 16; kv = kv1; lcw = lcw1; lcb = lcb1;
        vh = v1h; vl = v1l;
    } else {
        token = blockIdx.x - BATCH * 256; HS = 8; kv = kv2; lcw = lcw2; lcb = lcb2;
        vh = v2h; vl = v2l;
    }
    const int NS = HS * HS;
    const int b  = token / NS;
    const int s  = token - b * NS;
    const int hs = s / HS, ws = s - hs * HS;
    const int c  = threadIdx.x;

    float acc = lcb[c];
#pragma unroll
    for (int kh = 0; kh < 3; kh++)
#pragma unroll
        for (int kw = 0; kw < 3; kw++) {
            const int ih = hs - 1 + kh, iw = ws - 1 + kw;
            if (ih >= 0 && ih < HS && iw >= 0 && iw < HS)
                acc += kv[((size_t)b * NS + ih * HS + iw) * 256 + 128 + c]
                     * lcw[c * 9 + kh * 3 + kw];
        }
    const float v = kv[(size_t)token * 256 + 128 + c] + acc;
    const int h = c >> 5, e = c & 31;
    const size_t o = (((size_t)b * 4 + h) * 32 + e) * NS + s;
    const __nv_bfloat16 hh = __float2bfloat16(v);
    vh[o] = hh;
    vl[o] = __float2bfloat16(v - __bfloat162float(hh));
}

// ---------------------------------------------------------------------------
// Flash attention: q/k bf16 hi-only; V hi/lo bf16 planes (no PRMT anywhere).
// 64 q / 256 threads / 2 blocks per SM.
// ---------------------------------------------------------------------------
template<int NS>
__device__ __forceinline__ void attn_body(
    const __nv_bfloat16* __restrict__ qh,
    const __nv_bfloat16* __restrict__ kh,
    const __nv_bfloat16* __restrict__ vh, const __nv_bfloat16* __restrict__ vl,
    uint32_t* __restrict__ catp,
    int qoff, int ooff, int bh, char* smc)
{
    constexpr int SCH = NS / 4;
    constexpr int NT2 = SCH / 8;
    constexpr int KT  = SCH / 16;
    constexpr int LDB = 40;            // bf16 row stride Q/K
    constexpr int VSP = NS + 8;        // bf16 row stride V planes (16B-aligned)
    constexpr int CHK8 = NS / 8;       // 16B chunks per V plane row
    // byte offsets
    constexpr int OFF_KS_B = 64 * LDB * 2;                 // 5120
    constexpr int OFF_VH_B = OFF_KS_B + NS * LDB * 2;
    constexpr int OFF_VL_B = OFF_VH_B + 32 * VSP * 2;
    constexpr int OFF_PB_B = OFF_VL_B + 32 * VSP * 2;
    constexpr int OFF_ST_B = OFF_PB_B + 8 * 32 * 34 * 4;
    const float kfac = 0.17677669529663689f * 1.4426950408889634f;

    __nv_bfloat16* Qs = (__nv_bfloat16*)smc;               // [64][LDB]
    __nv_bfloat16* Ks = (__nv_bfloat16*)(smc + OFF_KS_B);  // [NS][LDB]
    __nv_bfloat16* Vh = (__nv_bfloat16*)(smc + OFF_VH_B);  // [32][VSP]
    __nv_bfloat16* Vl = (__nv_bfloat16*)(smc + OFF_VL_B);  // [32][VSP]
    float*         pb = (float*)(smc + OFF_PB_B);          // [8][32][34]
    float*         mx = (float*)(smc + OFF_ST_B);          // [4][64]
    float*        smr = mx + 256;                          // [4][64]

    const int b = bh >> 2, h = bh & 3;
    const int q0 = blockIdx.y * 64;
    const int tid = threadIdx.x, lane = tid & 31, w = tid >> 5;
    const int g = lane >> 2, qk = (lane & 3) * 2;
    const int wm = w >> 2, wn = w & 3;

    // async staging: Q+K bf16 (group 0), V planes (group 1)
    {
        const int r = tid >> 2, cw = tid & 3;
        cpa16(&Qs[r * LDB + cw * 8],
              &qh[((size_t)(b * 4096 + q0 + r)) * 256 + qoff + h * 32 + cw * 8]);
    }
    for (int c = tid; c < NS * 4; c += 256) {
        const int s = c >> 2, cw = c & 3;
        cpa16(&Ks[s * LDB + cw * 8],
              &kh[((size_t)(b * NS + s)) * 128 + h * 32 + cw * 8]);
    }
    asm volatile("cp.async.commit_group;\n" ::: "memory");
    for (int c = tid; c < 32 * CHK8; c += 256) {
        const int e = c / CHK8, s8 = c % CHK8;
        const size_t src = (((size_t)(b * 4 + h)) * 32 + e) * NS + s8 * 8;
        cpa16(&Vh[e * VSP + s8 * 8], &vh[src]);
        cpa16(&Vl[e * VSP + s8 * 8], &vl[src]);
    }
    asm volatile("cp.async.commit_group;\n" ::: "memory");
    asm volatile("cp.async.wait_group 1;\n" ::: "memory");
    __syncthreads();

    // phase 1: S = Q K^T (hi-only, direct LDS.32)
    float acc[2][NT2][4];
#pragma unroll
    for (int mt = 0; mt < 2; mt++)
#pragma unroll
        for (int nt = 0; nt < NT2; nt++)
#pragma unroll
            for (int r = 0; r < 4; r++) acc[mt][nt][r] = 0.f;

#pragma unroll
    for (int kc = 0; kc < 2; kc++) {
        const int kb = kc * 16;
        uint32_t ah[2][4];
#pragma unroll
        for (int mt = 0; mt < 2; mt++) {
            const int row = wm * 32 + mt * 16 + g;
            const int o0 = row * LDB + kb + qk;
            ah[mt][0] = *(const uint32_t*)&Qs[o0];
            ah[mt][1] = *(const uint32_t*)&Qs[o0 + 8 * LDB];
            ah[mt][2] = *(const uint32_t*)&Qs[o0 + 8];
            ah[mt][3] = *(const uint32_t*)&Qs[o0 + 8 * LDB + 8];
        }
#pragma unroll
        for (int nt = 0; nt < NT2; nt++) {
            const int srow = wn * SCH + nt * 8 + g;
            const int o0 = srow * LDB + kb + qk;
            uint32_t bh2[2];
            bh2[0] = *(const uint32_t*)&Ks[o0];
            bh2[1] = *(const uint32_t*)&Ks[o0 + 8];
#pragma unroll
            for (int mt = 0; mt < 2; mt++)
                mma16816(acc[mt][nt], ah[mt], bh2);
        }
    }

    // chunk max
#pragma unroll
    for (int mt = 0; mt < 2; mt++)
#pragma unroll
        for (int half = 0; half < 2; half++) {
            float m = acc[mt][0][half * 2];
#pragma unroll
            for (int nt = 0; nt < NT2; nt++) {
                m = fmaxf(m, acc[mt][nt][half * 2]);
                m = fmaxf(m, acc[mt][nt][half * 2 + 1]);
            }
            m = fmaxf(m, __shfl_xor_sync(0xffffffffu, m, 1));
            m = fmaxf(m, __shfl_xor_sync(0xffffffffu, m, 2));
            if ((lane & 3) == 0)
                mx[wn * 64 + wm * 32 + mt * 16 + half * 8 + g] = m;
        }
    __syncthreads();   // barrier 1

    // global max, exp, chunk sums
#pragma unroll
    for (int mt = 0; mt < 2; mt++)
#pragma unroll
        for (int half = 0; half < 2; half++) {
            const int row = wm * 32 + mt * 16 + half * 8 + g;
            float m = fmaxf(fmaxf(mx[row], mx[64 + row]),
                            fmaxf(mx[128 + row], mx[192 + row]));
            float s = 0.f;
#pragma unroll
            for (int nt = 0; nt < NT2; nt++) {
                float e0 = exp2f((acc[mt][nt][half * 2]     - m) * kfac);
                float e1 = exp2f((acc[mt][nt][half * 2 + 1] - m) * kfac);
                acc[mt][nt][half * 2]     = e0;
                acc[mt][nt][half * 2 + 1] = e1;
                s += e0 + e1;
            }
            s += __shfl_xor_sync(0xffffffffu, s, 1);
            s += __shfl_xor_sync(0xffffffffu, s, 2);
            if ((lane & 3) == 0) smr[wn * 64 + row] = s;
        }
    asm volatile("cp.async.wait_group 0;\n" ::: "memory");
    __syncthreads();   // barrier 2

    // phase 3: O_partial = P V (3-term; V plane loads, no PRMT)
    float acc3[2][4][4];
#pragma unroll
    for (int mt = 0; mt < 2; mt++)
#pragma unroll
        for (int nt = 0; nt < 4; nt++)
#pragma unroll
            for (int r = 0; r < 4; r++) acc3[mt][nt][r] = 0.f;

#pragma unroll
    for (int kt = 0; kt < KT; kt++) {
        uint32_t bh3[4][2], bl3[4][2];
#pragma unroll
        for (int nt3 = 0; nt3 < 4; nt3++) {
            const int e = nt3 * 8 + g;
            const int base = e * VSP + wn * SCH + kt * 16 + qk;
            bh3[nt3][0] = *(const uint32_t*)&Vh[base];
            bh3[nt3][1] = *(const uint32_t*)&Vh[base + 8];
            bl3[nt3][0] = *(const uint32_t*)&Vl[base];
            bl3[nt3][1] = *(const uint32_t*)&Vl[base + 8];
        }
#pragma unroll
        for (int mt = 0; mt < 2; mt++) {
            uint32_t ah[4], al[4];
            pack2_hilo(acc[mt][2 * kt][0],     acc[mt][2 * kt][1],     ah[0], al[0]);
            pack2_hilo(acc[mt][2 * kt][2],     acc[mt][2 * kt][3],     ah[1], al[1]);
            pack2_hilo(acc[mt][2 * kt + 1][0], acc[mt][2 * kt + 1][1], ah[2], al[2]);
            pack2_hilo(acc[mt][2 * kt + 1][2], acc[mt][2 * kt + 1][3], ah[3], al[3]);
#pragma unroll
            for (int nt3 = 0; nt3 < 4; nt3++) {
                mma16816(acc3[mt][nt3], ah, bh3[nt3]);
                mma16816(acc3[mt][nt3], al, bh3[nt3]);
                mma16816(acc3[mt][nt3], ah, bl3[nt3]);
            }
        }
    }

    // write partials (slot = wn*2 + wm)
#pragma unroll
    for (int mt = 0; mt < 2; mt++)
#pragma unroll
        for (int nt3 = 0; nt3 < 4; nt3++) {
            const int rl = mt * 16 + g;
            const int base = ((wn * 2 + wm) * 32 + rl) * 34 + nt3 * 8 + qk;
            *(float2*)&pb[base] = make_float2(acc3[mt][nt3][0], acc3[mt][nt3][1]);
            *(float2*)&pb[base + 8 * 34] = make_float2(acc3[mt][nt3][2], acc3[mt][nt3][3]);
        }
    __syncthreads();   // barrier 3

    // reduction + epilogue
#pragma unroll
    for (int rr = 0; rr < 4; rr++) {
        const int rloc = rr * 8 + (lane >> 2);
        const int row = wm * 32 + rloc;
        const int cl = wn * 8 + (lane & 3) * 2;
        float ox = 0.f, oy = 0.f;
#pragma unroll
        for (int wv = 0; wv < 4; wv++) {
            float2 p = *(const float2*)&pb[((wv * 2 + wm) * 32 + rloc) * 34 + cl];
            ox += p.x; oy += p.y;
        }
        const float inv = 1.0f / (smr[row] + smr[64 + row] +
                                  smr[128 + row] + smr[192 + row]);
        const int col = ooff + h * 32 + cl;
        *(uint2*)&catp[((size_t)(b * 4096 + q0 + row)) * 256 + col] =
            make_uint2(pack_hilo(ox * inv), pack_hilo(oy * inv));
    }
}

__global__ __launch_bounds__(256, 2) void attn_b1(
    const __nv_bfloat16* __restrict__ qh, const __nv_bfloat16* __restrict__ kh,
    const __nv_bfloat16* __restrict__ vh, const __nv_bfloat16* __restrict__ vl,
    uint32_t* __restrict__ catp)
{
    extern __shared__ char smc[];
    attn_body<256>(qh, kh, vh, vl, catp, 0, 0, blockIdx.x, smc);
}

__global__ __launch_bounds__(256, 2) void attn_b2(
    const __nv_bfloat16* __restrict__ qh, const __nv_bfloat16* __restrict__ kh,
    const __nv_bfloat16* __restrict__ vh, const __nv_bfloat16* __restrict__ vl,
    uint32_t* __restrict__ catp)
{
    extern __shared__ char smc[];
    attn_body<64>(qh, kh, vh, vl, catp, 128, 128, blockIdx.x, smc);
}

// ---------------------------------------------------------------------------
// launch
// ---------------------------------------------------------------------------
extern "C" void kernel_launch(void* const* d_in, const int* in_sizes, int n_in,
                              void* d_out, int out_size)
{
    const float* x      = (const float*)d_in[0];
    const float* q_w    = (const float*)d_in[1];
    const float* kv1_w  = (const float*)d_in[2];
    const float* kv2_w  = (const float*)d_in[3];
    const float* proj_w = (const float*)d_in[4];
    const float* proj_b = (const float*)d_in[5];
    const float* sr1_w  = (const float*)d_in[6];
    const float* sr1_b  = (const float*)d_in[7];
    const float* sr2_w  = (const float*)d_in[8];
    const float* sr2_b  = (const float*)d_in[9];
    const float* ln1_g  = (const float*)d_in[10];
    const float* ln1_b  = (const float*)d_in[11];
    const float* ln2_g  = (const float*)d_in[12];
    const float* ln2_b  = (const float*)d_in[13];
    const float* lc1_w  = (const float*)d_in[14];
    const float* lc1_b  = (const float*)d_in[15];
    const float* lc2_w  = (const float*)d_in[16];
    const float* lc2_b  = (const float*)d_in[17];
    float* out = (float*)d_out;

    uint32_t *p_catp, *p_x1p, *p_x2p;
    float *p_kv1, *p_kv2;
    __nv_bfloat16 *p_xh, *p_qh, *p_k1h, *p_k2h;
    __nv_bfloat16 *p_v1h, *p_v1l, *p_v2h, *p_v2l;
    __nv_bfloat16 *p_qwh, *p_qwl, *p_k1wh, *p_k1wl, *p_k2wh, *p_k2wl, *p_pwh, *p_pwl;
    cudaGetSymbolAddress((void**)&p_xh,   g_xh);
    cudaGetSymbolAddress((void**)&p_qh,   g_qh);
    cudaGetSymbolAddress((void**)&p_catp, g_catp);
    cudaGetSymbolAddress((void**)&p_x1p,  g_x1p);
    cudaGetSymbolAddress((void**)&p_x2p,  g_x2p);
    cudaGetSymbolAddress((void**)&p_kv1,  g_kv1);
    cudaGetSymbolAddress((void**)&p_kv2,  g_kv2);
    cudaGetSymbolAddress((void**)&p_k1h,  g_k1h);
    cudaGetSymbolAddress((void**)&p_k2h,  g_k2h);
    cudaGetSymbolAddress((void**)&p_v1h,  g_v1h);
    cudaGetSymbolAddress((void**)&p_v1l,  g_v1l);
    cudaGetSymbolAddress((void**)&p_v2h,  g_v2h);
    cudaGetSymbolAddress((void**)&p_v2l,  g_v2l);
    cudaGetSymbolAddress((void**)&p_qwh,  g_qwh);
    cudaGetSymbolAddress((void**)&p_qwl,  g_qwl);
    cudaGetSymbolAddress((void**)&p_k1wh, g_k1wh);
    cudaGetSymbolAddress((void**)&p_k1wl, g_k1wl);
    cudaGetSymbolAddress((void**)&p_k2wh, g_k2wh);
    cudaGetSymbolAddress((void**)&p_k2wl, g_k2wl);
    cudaGetSymbolAddress((void**)&p_pwh,  g_pwh);
    cudaGetSymbolAddress((void**)&p_pwl,  g_pwl);

    const int smem_gemm = 3 * (128 * 40 * 4) + 2 * (3 * 256 * 40 * 2);  // 184,320
    const int smem_dw   = 80 * 257 * 4 + 128;
    // attn smem bytes: Q 5120 + K NS*80 + Vh/Vl 32*(NS+8)*2 each + pb 34816 + stats 2048
    const int smem_a1 = 5120 + 256 * 80 + 2 * (32 * 264 * 2) + 34816 + 2048;  // 96,256
    const int smem_a2 = 5120 + 64 * 80 + 2 * (32 * 72 * 2) + 34816 + 2048;    // 56,320
    cudaFuncSetAttribute(gemm_all,  cudaFuncAttributeMaxDynamicSharedMemorySize, smem_gemm);
    cudaFuncSetAttribute(gemm_proj, cudaFuncAttributeMaxDynamicSharedMemorySize, smem_gemm);
    cudaFuncSetAttribute(dwconv_wsplit, cudaFuncAttributeMaxDynamicSharedMemorySize, smem_dw);
    cudaFuncSetAttribute(attn_b1, cudaFuncAttributeMaxDynamicSharedMemorySize, smem_a1);
    cudaFuncSetAttribute(attn_b2, cudaFuncAttributeMaxDynamicSharedMemorySize, smem_a2);

    // 0: dwconv (+x hi) + weight split
    dwconv_wsplit<<<768, 512, smem_dw>>>(
        x, p_xh, sr1_w, sr1_b, ln1_g, ln1_b, sr2_w, sr2_b, ln2_g, ln2_b,
        p_x1p, p_x2p,
        q_w, kv1_w, kv2_w, proj_w,
        p_qwh, p_qwl, p_k1wh, p_k1wl, p_k2wh, p_k2wl, p_pwh, p_pwl);
    // 1: all projections (q 256 [1-term] + kv1 16 + kv2 4 blocks)
    gemm_all<<<276, 512, smem_gemm>>>(
        p_xh, p_x1p, p_x2p, p_qwh,
        p_k1wh, p_k1wl, p_k2wh, p_k2wl,
        p_qh, p_kv1, p_k1h, p_kv2, p_k2h);
    // 2: v local conv -> V^T hi/lo planes
    vconv_fused<<<BATCH * 256 + BATCH * 64, 128>>>(
        p_kv1, lc1_w, lc1_b, p_v1h, p_v1l,
        p_kv2, lc2_w, lc2_b, p_v2h, p_v2l);
    // 3: attention branch 1 (PROFILED SLOT)
    attn_b1<<<dim3(32, 64), 256, smem_a1>>>(p_qh, p_k1h, p_v1h, p_v1l, p_catp);
    // 4: attention branch 2
    attn_b2<<<dim3(32, 64), 256, smem_a2>>>(p_qh, p_k2h, p_v2h, p_v2l, p_catp);
    // 5: output projection
    gemm_proj<<<256, 512, smem_gemm>>>(p_catp, p_pwh, p_pwl, proj_b, out);
}

// round 17
// speedup vs baseline: 1.3190x; 1.0846x over previous
#include <cuda_runtime.h>
#include <cuda_bf16.h>
#include <cuda_fp16.h>
#include <cstdint>

// Problem constants: B=8, H=W=64, N=4096, C=256, nh=8, nh2=4, hd=32, sr=8
#define BATCH 8
#define NTOK 4096
#define CH 256

// ---------------------------------------------------------------------------
// Scratch (device globals)
// ---------------------------------------------------------------------------
__device__ __half        g_xh  [(size_t)BATCH * NTOK * CH];   // x fp16 (q-gemm A)
__device__ __half        g_qh  [(size_t)BATCH * NTOK * CH];   // q fp16
__device__ uint32_t      g_catp[(size_t)BATCH * NTOK * CH];   // cat packed bf16 (hi,lo)
__device__ uint32_t      g_x1p [BATCH * 256 * CH];
__device__ uint32_t      g_x2p [BATCH * 64 * CH];
__device__ float         g_kv1 [BATCH * 256 * CH];
__device__ float         g_kv2 [BATCH * 64 * CH];
__device__ __half        g_k1h [BATCH * 256 * 128];           // k fp16
__device__ __half        g_k2h [BATCH * 64 * 128];
__device__ __half        g_v1h [BATCH * 4 * 32 * 256];        // V^T fp16 single plane
__device__ __half        g_v2h [BATCH * 4 * 32 * 64];
// weights: q fp16 plane; kv/proj bf16 hi/lo planes
__device__ __half        g_qwf [256 * 256];
__device__ __nv_bfloat16 g_k1wh[256 * 256], g_k1wl[256 * 256];
__device__ __nv_bfloat16 g_k2wh[256 * 256], g_k2wl[256 * 256];
__device__ __nv_bfloat16 g_pwh [256 * 256], g_pwl [256 * 256];

// ---------------------------------------------------------------------------
// helpers
// ---------------------------------------------------------------------------
__device__ __forceinline__ uint32_t pack_hilo(float v) {
    __nv_bfloat16 h = __float2bfloat16(v);
    __nv_bfloat16 l = __float2bfloat16(v - __bfloat162float(h));
    return (uint32_t)__bfloat16_as_ushort(h) |
           ((uint32_t)__bfloat16_as_ushort(l) << 16);
}

// Two fp32 -> fp16x2 (elem0 in low half).
__device__ __forceinline__ uint32_t pack_f16x2(float p0, float p1) {
    uint32_t r;
    asm("cvt.rn.f16x2.f32 %0, %1, %2;" : "=r"(r) : "f"(p1), "f"(p0));
    return r;
}

__device__ __forceinline__ void mma16816(
    float* c, const uint32_t* a, const uint32_t* b)
{
    asm volatile(
        "mma.sync.aligned.m16n8k16.row.col.f32.bf16.bf16.f32 "
        "{%0,%1,%2,%3}, {%4,%5,%6,%7}, {%8,%9}, {%0,%1,%2,%3};"
        : "+f"(c[0]), "+f"(c[1]), "+f"(c[2]), "+f"(c[3])
        : "r"(a[0]), "r"(a[1]), "r"(a[2]), "r"(a[3]), "r"(b[0]), "r"(b[1]));
}

__device__ __forceinline__ void mma16816h(
    float* c, const uint32_t* a, const uint32_t* b)
{
    asm volatile(
        "mma.sync.aligned.m16n8k16.row.col.f32.f16.f16.f32 "
        "{%0,%1,%2,%3}, {%4,%5,%6,%7}, {%8,%9}, {%0,%1,%2,%3};"
        : "+f"(c[0]), "+f"(c[1]), "+f"(c[2]), "+f"(c[3])
        : "r"(a[0]), "r"(a[1]), "r"(a[2]), "r"(a[3]), "r"(b[0]), "r"(b[1]));
}

__device__ __forceinline__ void cpa16(void* dst, const void* src) {
    uint32_t d = (uint32_t)__cvta_generic_to_shared(dst);
    asm volatile("cp.async.cg.shared.global [%0], [%1], 16;\n"
                 :: "r"(d), "l"(src));
}

// ---------------------------------------------------------------------------
// q-GEMM body: single-term fp16. A fp16 [M,256], W fp16 [256,256].
// 512 threads, 128x256 tile, 3-stage cp.async. 16 warps = 4m x 4n.
// ---------------------------------------------------------------------------
__device__ __forceinline__ void gemm_q_body(
    const __half* __restrict__ Ag,
    const __half* __restrict__ Wf,
    __half* __restrict__ Cb,
    int m0, char* smraw)
{
    constexpr int LD  = 40;
    constexpr int ASZ = 128 * LD;
    constexpr int BSZ = 256 * LD;
    __half* Ah = (__half*)smraw;   // [3][128][LD]
    __half* Bh = Ah + 3 * ASZ;     // [3][256][LD]

    const int tid = threadIdx.x;
    const int w = tid >> 5, lane = tid & 31;
    const int wm = w & 3, wn = w >> 2;
    const int g = lane >> 2, qk = (lane & 3) * 2;

    auto load_stage = [&](int s, int k0) {
        {
            const int row = tid >> 2, ch = tid & 3;
            cpa16(&Ah[s * ASZ + row * LD + ch * 8],
                  &Ag[(size_t)(m0 + row) * 256 + k0 + ch * 8]);
        }
#pragma unroll
        for (int i = 0; i < 2; i++) {
            const int c = tid + i * 512;
            const int row = c >> 2, ch = c & 3;
            cpa16(&Bh[s * BSZ + row * LD + ch * 8],
                  &Wf[(size_t)row * 256 + k0 + ch * 8]);
        }
        asm volatile("cp.async.commit_group;\n" ::: "memory");
    };

    float acc[2][8][4];
#pragma unroll
    for (int mt = 0; mt < 2; mt++)
#pragma unroll
        for (int nt = 0; nt < 8; nt++)
#pragma unroll
            for (int r = 0; r < 4; r++) acc[mt][nt][r] = 0.f;

    load_stage(0, 0);
    load_stage(1, 32);

    for (int it = 0; it < 8; it++) {
        if (it < 7) asm volatile("cp.async.wait_group 1;\n" ::: "memory");
        else        asm volatile("cp.async.wait_group 0;\n" ::: "memory");
        __syncthreads();
        if (it + 2 < 8) load_stage((it + 2) % 3, (it + 2) * 32);

        const int s = it % 3;
        const __half* Ahs = Ah + s * ASZ;
        const __half* Bhs = Bh + s * BSZ;

#pragma unroll
        for (int ks = 0; ks < 2; ks++) {
            const int kb = ks * 16;
            uint32_t ah[2][4];
#pragma unroll
            for (int mt = 0; mt < 2; mt++) {
                const int row = wm * 32 + mt * 16 + g;
                const int o0 = row * LD + kb + qk;
                ah[mt][0] = *(const uint32_t*)&Ahs[o0];
                ah[mt][1] = *(const uint32_t*)&Ahs[o0 + 8 * LD];
                ah[mt][2] = *(const uint32_t*)&Ahs[o0 + 8];
                ah[mt][3] = *(const uint32_t*)&Ahs[o0 + 8 * LD + 8];
            }
#pragma unroll
            for (int nt = 0; nt < 8; nt++) {
                const __half* pb = &Bhs[(wn * 64 + nt * 8 + g) * LD + kb + qk];
                uint32_t bf[2];
                bf[0] = *(const uint32_t*)pb;
                bf[1] = *(const uint32_t*)(pb + 8);
#pragma unroll
                for (int mt = 0; mt < 2; mt++)
                    mma16816h(acc[mt][nt], ah[mt], bf);
            }
        }
        __syncthreads();
    }

#pragma unroll
    for (int mt = 0; mt < 2; mt++) {
        const int r = m0 + wm * 32 + mt * 16 + g;
#pragma unroll
        for (int nt = 0; nt < 8; nt++) {
            const int col = wn * 64 + nt * 8 + qk;
            *(uint32_t*)&Cb[(size_t)r * 256 + col] =
                pack_f16x2(acc[mt][nt][0], acc[mt][nt][1]);
            *(uint32_t*)&Cb[(size_t)(r + 8) * 256 + col] =
                pack_f16x2(acc[mt][nt][2], acc[mt][nt][3]);
        }
    }
}

// ---------------------------------------------------------------------------
// Full GEMM body (3-term bf16, A packed u32): MODE 0 fp32+bias, MODE 2
// fp32 + k-half as fp16.
// ---------------------------------------------------------------------------
template<int MODE>
__device__ __forceinline__ void gemm_body(
    const uint32_t* __restrict__ A,
    const __nv_bfloat16* __restrict__ Wh,
    const __nv_bfloat16* __restrict__ Wl,
    const float* __restrict__ bias,
    float* __restrict__ Cf, __half* __restrict__ Cb,
    int m0, char* smraw)
{
    constexpr int LDA = 40;
    constexpr int LDB = 40;
    constexpr int ASZ = 128 * LDA;
    constexpr int BSZ = 256 * LDB;

    uint32_t*      Ap = (uint32_t*)smraw;
    __nv_bfloat16* Bh = (__nv_bfloat16*)(Ap + 3 * ASZ);
    __nv_bfloat16* Bl = Bh + 3 * BSZ;

    const int tid = threadIdx.x;
    const int w = tid >> 5, lane = tid & 31;
    const int wm = w & 3, wn = w >> 2;
    const int g = lane >> 2, qk = (lane & 3) * 2;

    auto load_stage = [&](int s, int k0) {
#pragma unroll
        for (int i = 0; i < 2; i++) {
            const int c = tid + i * 512;
            const int row = c >> 3, ch = c & 7;
            cpa16(&Ap[s * ASZ + row * LDA + ch * 4],
                  &A[(size_t)(m0 + row) * 256 + k0 + ch * 4]);
        }
#pragma unroll
        for (int i = 0; i < 2; i++) {
            const int c = tid + i * 512;
            const int row = c >> 2, ch = c & 3;
            cpa16(&Bh[s * BSZ + row * LDB + ch * 8],
                  &Wh[(size_t)row * 256 + k0 + ch * 8]);
        }
#pragma unroll
        for (int i = 0; i < 2; i++) {
            const int c = tid + i * 512;
            const int row = c >> 2, ch = c & 3;
            cpa16(&Bl[s * BSZ + row * LDB + ch * 8],
                  &Wl[(size_t)row * 256 + k0 + ch * 8]);
        }
        asm volatile("cp.async.commit_group;\n" ::: "memory");
    };

    float acc[2][8][4];
#pragma unroll
    for (int mt = 0; mt < 2; mt++)
#pragma unroll
        for (int nt = 0; nt < 8; nt++)
#pragma unroll
            for (int r = 0; r < 4; r++) acc[mt][nt][r] = 0.f;

    load_stage(0, 0);
    load_stage(1, 32);

    for (int it = 0; it < 8; it++) {
        if (it < 7) asm volatile("cp.async.wait_group 1;\n" ::: "memory");
        else        asm volatile("cp.async.wait_group 0;\n" ::: "memory");
        __syncthreads();
        if (it + 2 < 8) load_stage((it + 2) % 3, (it + 2) * 32);

        const int s = it % 3;
        const uint32_t*      As  = Ap + s * ASZ;
        const __nv_bfloat16* Bhs = Bh + s * BSZ;
        const __nv_bfloat16* Bls = Bl + s * BSZ;

#pragma unroll
        for (int ks = 0; ks < 2; ks++) {
            const int kb = ks * 16;
            uint32_t ah[2][4], al[2][4];
#pragma unroll
            for (int mt = 0; mt < 2; mt++) {
                const int row = wm * 32 + mt * 16 + g;
                uint2 p0 = *(const uint2*)&As[row * LDA + kb + qk];
                uint2 p1 = *(const uint2*)&As[(row + 8) * LDA + kb + qk];
                uint2 p2 = *(const uint2*)&As[row * LDA + kb + qk + 8];
                uint2 p3 = *(const uint2*)&As[(row + 8) * LDA + kb + qk + 8];
                ah[mt][0] = __byte_perm(p0.x, p0.y, 0x5410);
                al[mt][0] = __byte_perm(p0.x, p0.y, 0x7632);
                ah[mt][1] = __byte_perm(p1.x, p1.y, 0x5410);
                al[mt][1] = __byte_perm(p1.x, p1.y, 0x7632);
                ah[mt][2] = __byte_perm(p2.x, p2.y, 0x5410);
                al[mt][2] = __byte_perm(p2.x, p2.y, 0x7632);
                ah[mt][3] = __byte_perm(p3.x, p3.y, 0x5410);
                al[mt][3] = __byte_perm(p3.x, p3.y, 0x7632);
            }
            uint32_t bf[8][2];
#pragma unroll
            for (int nt = 0; nt < 8; nt++) {
                const __nv_bfloat16* pb = &Bhs[(wn * 64 + nt * 8 + g) * LDB + kb + qk];
                bf[nt][0] = *(const uint32_t*)pb;
                bf[nt][1] = *(const uint32_t*)(pb + 8);
            }
#pragma unroll
            for (int mt = 0; mt < 2; mt++)
#pragma unroll
                for (int nt = 0; nt < 8; nt++) {
                    mma16816(acc[mt][nt], ah[mt], bf[nt]);
                    mma16816(acc[mt][nt], al[mt], bf[nt]);
                }
#pragma unroll
            for (int nt = 0; nt < 8; nt++) {
                const __nv_bfloat16* pb = &Bls[(wn * 64 + nt * 8 + g) * LDB + kb + qk];
                bf[nt][0] = *(const uint32_t*)pb;
                bf[nt][1] = *(const uint32_t*)(pb + 8);
            }
#pragma unroll
            for (int mt = 0; mt < 2; mt++)
#pragma unroll
                for (int nt = 0; nt < 8; nt++)
                    mma16816(acc[mt][nt], ah[mt], bf[nt]);
        }
        __syncthreads();
    }

#pragma unroll
    for (int mt = 0; mt < 2; mt++) {
        const int r = m0 + wm * 32 + mt * 16 + g;
#pragma unroll
        for (int nt = 0; nt < 8; nt++) {
            const int col = wn * 64 + nt * 8 + qk;
            if constexpr (MODE == 0) {
                const float b0 = bias[col], b1 = bias[col + 1];
                *(float2*)&Cf[(size_t)r * 256 + col] =
                    make_float2(acc[mt][nt][0] + b0, acc[mt][nt][1] + b1);
                *(float2*)&Cf[(size_t)(r + 8) * 256 + col] =
                    make_float2(acc[mt][nt][2] + b0, acc[mt][nt][3] + b1);
            } else {
                *(float2*)&Cf[(size_t)r * 256 + col] =
                    make_float2(acc[mt][nt][0], acc[mt][nt][1]);
                *(float2*)&Cf[(size_t)(r + 8) * 256 + col] =
                    make_float2(acc[mt][nt][2], acc[mt][nt][3]);
                if (col < 128) {
                    *(uint32_t*)&Cb[(size_t)r * 128 + col] =
                        pack_f16x2(acc[mt][nt][0], acc[mt][nt][1]);
                    *(uint32_t*)&Cb[(size_t)(r + 8) * 128 + col] =
                        pack_f16x2(acc[mt][nt][2], acc[mt][nt][3]);
                }
            }
        }
    }
}

// Combined projection GEMMs: q (256 blocks, fp16 1-term) + kv1 (16) + kv2 (4).
__global__ __launch_bounds__(512) void gemm_all(
    const __half* __restrict__ xh,
    const uint32_t* __restrict__ x1p, const uint32_t* __restrict__ x2p,
    const __half* __restrict__ qwf,
    const __nv_bfloat16* __restrict__ k1wh, const __nv_bfloat16* __restrict__ k1wl,
    const __nv_bfloat16* __restrict__ k2wh, const __nv_bfloat16* __restrict__ k2wl,
    __half* __restrict__ qh,
    float* __restrict__ kv1, __half* __restrict__ k1h,
    float* __restrict__ kv2, __half* __restrict__ k2h)
{
    extern __shared__ __align__(16) char smraw[];
    if (blockIdx.x < 256)
        gemm_q_body(xh, qwf, qh, blockIdx.x * 128, smraw);
    else if (blockIdx.x < 272)
        gemm_body<2>(x1p, k1wh, k1wl, nullptr, kv1, k1h, (blockIdx.x - 256) * 128, smraw);
    else
        gemm_body<2>(x2p, k2wh, k2wl, nullptr, kv2, k2h, (blockIdx.x - 272) * 128, smraw);
}

// Output projection (full precision 3-term).
__global__ __launch_bounds__(512) void gemm_proj(
    const uint32_t* __restrict__ A,
    const __nv_bfloat16* __restrict__ Wh, const __nv_bfloat16* __restrict__ Wl,
    const float* __restrict__ bias, float* __restrict__ Cf)
{
    extern __shared__ __align__(16) char smraw[];
    gemm_body<0>(A, Wh, Wl, bias, Cf, nullptr, blockIdx.x * 128, smraw);
}

// ---------------------------------------------------------------------------
// LN + exact GELU block helper
// ---------------------------------------------------------------------------
__device__ __forceinline__ float ln_gelu_block(
    float a, const float* __restrict__ g, const float* __restrict__ bln,
    float* red, int c)
{
    float s1 = a, s2 = a * a;
#pragma unroll
    for (int o = 16; o > 0; o >>= 1) {
        s1 += __shfl_xor_sync(0xffffffffu, s1, o);
        s2 += __shfl_xor_sync(0xffffffffu, s2, o);
    }
    if ((c & 31) == 0) { red[c >> 5] = s1; red[8 + (c >> 5)] = s2; }
    __syncthreads();
    if (c == 0) {
        float a0 = 0.f, b0 = 0.f;
#pragma unroll
        for (int i = 0; i < 8; i++) { a0 += red[i]; b0 += red[8 + i]; }
        red[0] = a0; red[8] = b0;
    }
    __syncthreads();
    const float mean = red[0] * (1.f / 256.f);
    const float var  = red[8] * (1.f / 256.f) - mean * mean;
    float y = (a - mean) * rsqrtf(var + 1e-5f) * g[c] + bln[c];
    y = 0.5f * y * (1.0f + erff(y * 0.70710678118654752f));
    __syncthreads();
    return y;
}

// ---------------------------------------------------------------------------
// dwconv_fused + x fp16 store + weight split (q -> fp16 plane; rest bf16 hi/lo)
// ---------------------------------------------------------------------------
__global__ __launch_bounds__(512, 2) void dwconv_wsplit(
    const float* __restrict__ x, __half* __restrict__ xh,
    const float* __restrict__ w1, const float* __restrict__ b1c,
    const float* __restrict__ g1, const float* __restrict__ bl1,
    const float* __restrict__ w2, const float* __restrict__ b2c,
    const float* __restrict__ g2, const float* __restrict__ bl2,
    uint32_t* __restrict__ x1p, uint32_t* __restrict__ x2p,
    const float* __restrict__ w0m, const float* __restrict__ w1m,
    const float* __restrict__ w2m, const float* __restrict__ w3m,
    __half* __restrict__ qwf,
    __nv_bfloat16* __restrict__ h1, __nv_bfloat16* __restrict__ l1,
    __nv_bfloat16* __restrict__ h2, __nv_bfloat16* __restrict__ l2,
    __nv_bfloat16* __restrict__ h3, __nv_bfloat16* __restrict__ l3)
{
    if (blockIdx.x >= 256) {
        const int widx = blockIdx.x - 256;
        const int which = widx >> 7;
        const int i = (widx & 127) * 512 + threadIdx.x;
        if (which == 0) {
            qwf[i] = __float2half(w0m[i]);
            return;
        }
        const float* in = which == 1 ? w1m : which == 2 ? w2m : w3m;
        __nv_bfloat16* oh = which == 1 ? h1 : which == 2 ? h2 : h3;
        __nv_bfloat16* ol = which == 1 ? l1 : which == 2 ? l2 : l3;
        const float v = in[i];
        const __nv_bfloat16 hi = __float2bfloat16(v);
        oh[i] = hi;
        ol[i] = __float2bfloat16(v - __bfloat162float(hi));
        return;
    }

    extern __shared__ float sw[];
    float* w2s = sw;
    float* w1s = sw + 64 * 257;
    float* redb = sw + 80 * 257;

    const int tid = threadIdx.x;
    const int c = tid & 255;
    const int win = tid >> 8;
    float* red = redb + win * 16;

    const int b = blockIdx.x >> 5;
    const int pair = blockIdx.x & 31;
    const int t2 = pair * 2 + win;
    const int oh2 = t2 >> 3, ow2 = t2 & 7;

    for (int i = tid; i < 64 * 256; i += 512)
        w2s[(i & 63) * 257 + (i >> 6)] = w2[i];
    for (int i = tid; i < 16 * 256; i += 512)
        w1s[(i & 15) * 257 + (i >> 4)] = w1[i];
    __syncthreads();

    float acc2 = b2c[c];
    float acc1[2][2];
    acc1[0][0] = acc1[0][1] = acc1[1][0] = acc1[1][1] = b1c[c];

#pragma unroll
    for (int kh = 0; kh < 8; kh++) {
#pragma unroll
        for (int kw = 0; kw < 8; kw++) {
            const int ih = oh2 * 8 + kh, iw = ow2 * 8 + kw;
            const size_t xi = ((size_t)b * NTOK + ih * 64 + iw) * CH + c;
            const float xv = x[xi];
            xh[xi] = __float2half(xv);
            acc2 += xv * w2s[(kh * 8 + kw) * 257 + c];
            acc1[kh >> 2][kw >> 2] += xv * w1s[((kh & 3) * 4 + (kw & 3)) * 257 + c];
        }
    }

    const float y2 = ln_gelu_block(acc2, g2, bl2, red, c);
    x2p[((size_t)b * 64 + t2) * CH + c] = pack_hilo(y2);
#pragma unroll
    for (int i = 0; i < 2; i++)
#pragma unroll
        for (int j = 0; j < 2; j++) {
            const float y1 = ln_gelu_block(acc1[i][j], g1, bl1, red, c);
            const int t1 = (oh2 * 2 + i) * 16 + (ow2 * 2 + j);
            x1p[((size_t)b * 256 + t1) * CH + c] = pack_hilo(y1);
        }
}

// ---------------------------------------------------------------------------
// Fused v local conv (+residual) -> V^T fp16 single plane [b,h][e][s]
// ---------------------------------------------------------------------------
__global__ __launch_bounds__(128) void vconv_fused(
    const float* __restrict__ kv1, const float* __restrict__ lcw1,
    const float* __restrict__ lcb1, __half* __restrict__ v1h,
    const float* __restrict__ kv2, const float* __restrict__ lcw2,
    const float* __restrict__ lcb2, __half* __restrict__ v2h)
{
    int token, HS;
    const float *kv, *lcw, *lcb;
    __half* vh;
    if (blockIdx.x < BATCH * 256) {
        token = blockIdx.x; HS = 16; kv = kv1; lcw = lcw1; lcb = lcb1; vh = v1h;
    } else {
        token = blockIdx.x - BATCH * 256; HS = 8; kv = kv2; lcw = lcw2; lcb = lcb2; vh = v2h;
    }
    const int NS = HS * HS;
    const int b  = token / NS;
    const int s  = token - b * NS;
    const int hs = s / HS, ws = s - hs * HS;
    const int c  = threadIdx.x;

    float acc = lcb[c];
#pragma unroll
    for (int kh = 0; kh < 3; kh++)
#pragma unroll
        for (int kw = 0; kw < 3; kw++) {
            const int ih = hs - 1 + kh, iw = ws - 1 + kw;
            if (ih >= 0 && ih < HS && iw >= 0 && iw < HS)
                acc += kv[((size_t)b * NS + ih * HS + iw) * 256 + 128 + c]
                     * lcw[c * 9 + kh * 3 + kw];
        }
    const float v = kv[(size_t)token * 256 + 128 + c] + acc;
    const int h = c >> 5, e = c & 31;
    vh[(((size_t)b * 4 + h) * 32 + e) * NS + s] = __float2half(v);
}

// ---------------------------------------------------------------------------
// Flash attention, all-fp16 operands: Q/K fp16, V fp16 single plane,
// P fp16 single-term PV. 64 q / 256 threads / 2 blocks per SM.
// ---------------------------------------------------------------------------
template<int NS>
__device__ __forceinline__ void attn_body(
    const __half* __restrict__ qh,
    const __half* __restrict__ kh,
    const __half* __restrict__ vh,
    uint32_t* __restrict__ catp,
    int qoff, int ooff, int bh, char* smc)
{
    constexpr int SCH = NS / 4;
    constexpr int NT2 = SCH / 8;
    constexpr int KT  = SCH / 16;
    constexpr int LDB = 40;            // fp16 row stride Q/K
    constexpr int VSP = NS + 8;        // fp16 row stride V (16B aligned)
    constexpr int CHK8 = NS / 8;       // 16B chunks per V row
    // byte offsets
    constexpr int OFF_KS_B = 64 * LDB * 2;                 // 5120
    constexpr int OFF_VH_B = OFF_KS_B + NS * LDB * 2;
    constexpr int OFF_PB_B = OFF_VH_B + 32 * VSP * 2;
    constexpr int OFF_ST_B = OFF_PB_B + 8 * 32 * 34 * 4;
    const float kfac = 0.17677669529663689f * 1.4426950408889634f;

    __half* Qs = (__half*)smc;               // [64][LDB]
    __half* Ks = (__half*)(smc + OFF_KS_B);  // [NS][LDB]
    __half* Vh = (__half*)(smc + OFF_VH_B);  // [32][VSP]
    float*  pb = (float*)(smc + OFF_PB_B);   // [8][32][34]
    float*  mx = (float*)(smc + OFF_ST_B);   // [4][64]
    float* smr = mx + 256;                   // [4][64]

    const int b = bh >> 2, h = bh & 3;
    const int q0 = blockIdx.y * 64;
    const int tid = threadIdx.x, lane = tid & 31, w = tid >> 5;
    const int g = lane >> 2, qk = (lane & 3) * 2;
    const int wm = w >> 2, wn = w & 3;

    // async staging: Q+K (group 0), V (group 1)
    {
        const int r = tid >> 2, cw = tid & 3;
        cpa16(&Qs[r * LDB + cw * 8],
              &qh[((size_t)(b * 4096 + q0 + r)) * 256 + qoff + h * 32 + cw * 8]);
    }
    for (int c = tid; c < NS * 4; c += 256) {
        const int s = c >> 2, cw = c & 3;
        cpa16(&Ks[s * LDB + cw * 8],
              &kh[((size_t)(b * NS + s)) * 128 + h * 32 + cw * 8]);
    }
    asm volatile("cp.async.commit_group;\n" ::: "memory");
    for (int c = tid; c < 32 * CHK8; c += 256) {
        const int e = c / CHK8, s8 = c % CHK8;
        cpa16(&Vh[e * VSP + s8 * 8],
              &vh[(((size_t)(b * 4 + h)) * 32 + e) * NS + s8 * 8]);
    }
    asm volatile("cp.async.commit_group;\n" ::: "memory");
    asm volatile("cp.async.wait_group 1;\n" ::: "memory");
    __syncthreads();

    // phase 1: S = Q K^T (fp16, direct LDS.32)
    float acc[2][NT2][4];
#pragma unroll
    for (int mt = 0; mt < 2; mt++)
#pragma unroll
        for (int nt = 0; nt < NT2; nt++)
#pragma unroll
            for (int r = 0; r < 4; r++) acc[mt][nt][r] = 0.f;

#pragma unroll
    for (int kc = 0; kc < 2; kc++) {
        const int kb = kc * 16;
        uint32_t ah[2][4];
#pragma unroll
        for (int mt = 0; mt < 2; mt++) {
            const int row = wm * 32 + mt * 16 + g;
            const int o0 = row * LDB + kb + qk;
            ah[mt][0] = *(const uint32_t*)&Qs[o0];
            ah[mt][1] = *(const uint32_t*)&Qs[o0 + 8 * LDB];
            ah[mt][2] = *(const uint32_t*)&Qs[o0 + 8];
            ah[mt][3] = *(const uint32_t*)&Qs[o0 + 8 * LDB + 8];
        }
#pragma unroll
        for (int nt = 0; nt < NT2; nt++) {
            const int srow = wn * SCH + nt * 8 + g;
            const int o0 = srow * LDB + kb + qk;
            uint32_t bh2[2];
            bh2[0] = *(const uint32_t*)&Ks[o0];
            bh2[1] = *(const uint32_t*)&Ks[o0 + 8];
#pragma unroll
            for (int mt = 0; mt < 2; mt++)
                mma16816h(acc[mt][nt], ah[mt], bh2);
        }
    }

    // chunk max
#pragma unroll
    for (int mt = 0; mt < 2; mt++)
#pragma unroll
        for (int half = 0; half < 2; half++) {
            float m = acc[mt][0][half * 2];
#pragma unroll
            for (int nt = 0; nt < NT2; nt++) {
                m = fmaxf(m, acc[mt][nt][half * 2]);
                m = fmaxf(m, acc[mt][nt][half * 2 + 1]);
            }
            m = fmaxf(m, __shfl_xor_sync(0xffffffffu, m, 1));
            m = fmaxf(m, __shfl_xor_sync(0xffffffffu, m, 2));
            if ((lane & 3) == 0)
                mx[wn * 64 + wm * 32 + mt * 16 + half * 8 + g] = m;
        }
    __syncthreads();   // barrier 1

    // global max, exp, chunk sums
#pragma unroll
    for (int mt = 0; mt < 2; mt++)
#pragma unroll
        for (int half = 0; half < 2; half++) {
            const int row = wm * 32 + mt * 16 + half * 8 + g;
            float m = fmaxf(fmaxf(mx[row], mx[64 + row]),
                            fmaxf(mx[128 + row], mx[192 + row]));
            float s = 0.f;
#pragma unroll
            for (int nt = 0; nt < NT2; nt++) {
                float e0 = exp2f((acc[mt][nt][half * 2]     - m) * kfac);
                float e1 = exp2f((acc[mt][nt][half * 2 + 1] - m) * kfac);
                acc[mt][nt][half * 2]     = e0;
                acc[mt][nt][half * 2 + 1] = e1;
                s += e0 + e1;
            }
            s += __shfl_xor_sync(0xffffffffu, s, 1);
            s += __shfl_xor_sync(0xffffffffu, s, 2);
            if ((lane & 3) == 0) smr[wn * 64 + row] = s;
        }
    asm volatile("cp.async.wait_group 0;\n" ::: "memory");
    __syncthreads();   // barrier 2

    // phase 3: O_partial = P V (single-term fp16)
    float acc3[2][4][4];
#pragma unroll
    for (int mt = 0; mt < 2; mt++)
#pragma unroll
        for (int nt = 0; nt < 4; nt++)
#pragma unroll
            for (int r = 0; r < 4; r++) acc3[mt][nt][r] = 0.f;

#pragma unroll
    for (int kt = 0; kt < KT; kt++) {
        uint32_t bh3[4][2];
#pragma unroll
        for (int nt3 = 0; nt3 < 4; nt3++) {
            const int e = nt3 * 8 + g;
            const int base = e * VSP + wn * SCH + kt * 16 + qk;
            bh3[nt3][0] = *(const uint32_t*)&Vh[base];
            bh3[nt3][1] = *(const uint32_t*)&Vh[base + 8];
        }
#pragma unroll
        for (int mt = 0; mt < 2; mt++) {
            uint32_t ah[4];
            ah[0] = pack_f16x2(acc[mt][2 * kt][0],     acc[mt][2 * kt][1]);
            ah[1] = pack_f16x2(acc[mt][2 * kt][2],     acc[mt][2 * kt][3]);
            ah[2] = pack_f16x2(acc[mt][2 * kt + 1][0], acc[mt][2 * kt + 1][1]);
            ah[3] = pack_f16x2(acc[mt][2 * kt + 1][2], acc[mt][2 * kt + 1][3]);
#pragma unroll
            for (int nt3 = 0; nt3 < 4; nt3++)
                mma16816h(acc3[mt][nt3], ah, bh3[nt3]);
        }
    }

    // write partials (slot = wn*2 + wm)
#pragma unroll
    for (int mt = 0; mt < 2; mt++)
#pragma unroll
        for (int nt3 = 0; nt3 < 4; nt3++) {
            const int rl = mt * 16 + g;
            const int base = ((wn * 2 + wm) * 32 + rl) * 34 + nt3 * 8 + qk;
            *(float2*)&pb[base] = make_float2(acc3[mt][nt3][0], acc3[mt][nt3][1]);
            *(float2*)&pb[base + 8 * 34] = make_float2(acc3[mt][nt3][2], acc3[mt][nt3][3]);
        }
    __syncthreads();   // barrier 3

    // reduction + epilogue
#pragma unroll
    for (int rr = 0; rr < 4; rr++) {
        const int rloc = rr * 8 + (lane >> 2);
        const int row = wm * 32 + rloc;
        const int cl = wn * 8 + (lane & 3) * 2;
        float ox = 0.f, oy = 0.f;
#pragma unroll
        for (int wv = 0; wv < 4; wv++) {
            float2 p = *(const float2*)&pb[((wv * 2 + wm) * 32 + rloc) * 34 + cl];
            ox += p.x; oy += p.y;
        }
        const float inv = 1.0f / (smr[row] + smr[64 + row] +
                                  smr[128 + row] + smr[192 + row]);
        const int col = ooff + h * 32 + cl;
        *(uint2*)&catp[((size_t)(b * 4096 + q0 + row)) * 256 + col] =
            make_uint2(pack_hilo(ox * inv), pack_hilo(oy * inv));
    }
}

__global__ __launch_bounds__(256, 2) void attn_b1(
    const __half* __restrict__ qh, const __half* __restrict__ kh,
    const __half* __restrict__ vh, uint32_t* __restrict__ catp)
{
    extern __shared__ char smc[];
    attn_body<256>(qh, kh, vh, catp, 0, 0, blockIdx.x, smc);
}

__global__ __launch_bounds__(256, 2) void attn_b2(
    const __half* __restrict__ qh, const __half* __restrict__ kh,
    const __half* __restrict__ vh, uint32_t* __restrict__ catp)
{
    extern __shared__ char smc[];
    attn_body<64>(qh, kh, vh, catp, 128, 128, blockIdx.x, smc);
}

// ---------------------------------------------------------------------------
// launch
// ---------------------------------------------------------------------------
extern "C" void kernel_launch(void* const* d_in, const int* in_sizes, int n_in,
                              void* d_out, int out_size)
{
    const float* x      = (const float*)d_in[0];
    const float* q_w    = (const float*)d_in[1];
    const float* kv1_w  = (const float*)d_in[2];
    const float* kv2_w  = (const float*)d_in[3];
    const float* proj_w = (const float*)d_in[4];
    const float* proj_b = (const float*)d_in[5];
    const float* sr1_w  = (const float*)d_in[6];
    const float* sr1_b  = (const float*)d_in[7];
    const float* sr2_w  = (const float*)d_in[8];
    const float* sr2_b  = (const float*)d_in[9];
    const float* ln1_g  = (const float*)d_in[10];
    const float* ln1_b  = (const float*)d_in[11];
    const float* ln2_g  = (const float*)d_in[12];
    const float* ln2_b  = (const float*)d_in[13];
    const float* lc1_w  = (const float*)d_in[14];
    const float* lc1_b  = (const float*)d_in[15];
    const float* lc2_w  = (const float*)d_in[16];
    const float* lc2_b  = (const float*)d_in[17];
    float* out = (float*)d_out;

    uint32_t *p_catp, *p_x1p, *p_x2p;
    float *p_kv1, *p_kv2;
    __half *p_xh, *p_qh, *p_k1h, *p_k2h, *p_v1h, *p_v2h, *p_qwf;
    __nv_bfloat16 *p_k1wh, *p_k1wl, *p_k2wh, *p_k2wl, *p_pwh, *p_pwl;
    cudaGetSymbolAddress((void**)&p_xh,   g_xh);
    cudaGetSymbolAddress((void**)&p_qh,   g_qh);
    cudaGetSymbolAddress((void**)&p_catp, g_catp);
    cudaGetSymbolAddress((void**)&p_x1p,  g_x1p);
    cudaGetSymbolAddress((void**)&p_x2p,  g_x2p);
    cudaGetSymbolAddress((void**)&p_kv1,  g_kv1);
    cudaGetSymbolAddress((void**)&p_kv2,  g_kv2);
    cudaGetSymbolAddress((void**)&p_k1h,  g_k1h);
    cudaGetSymbolAddress((void**)&p_k2h,  g_k2h);
    cudaGetSymbolAddress((void**)&p_v1h,  g_v1h);
    cudaGetSymbolAddress((void**)&p_v2h,  g_v2h);
    cudaGetSymbolAddress((void**)&p_qwf,  g_qwf);
    cudaGetSymbolAddress((void**)&p_k1wh, g_k1wh);
    cudaGetSymbolAddress((void**)&p_k1wl, g_k1wl);
    cudaGetSymbolAddress((void**)&p_k2wh, g_k2wh);
    cudaGetSymbolAddress((void**)&p_k2wl, g_k2wl);
    cudaGetSymbolAddress((void**)&p_pwh,  g_pwh);
    cudaGetSymbolAddress((void**)&p_pwl,  g_pwl);

    const int smem_gemm = 3 * (128 * 40 * 4) + 2 * (3 * 256 * 40 * 2);  // 184,320
    const int smem_dw   = 80 * 257 * 4 + 128;
    // attn smem: Q 5120 + K NS*80 + V 32*(NS+8)*2 + pb 34816 + stats 2048
    const int smem_a1 = 5120 + 256 * 80 + 32 * 264 * 2 + 34816 + 2048;  // 79,360
    const int smem_a2 = 5120 + 64 * 80 + 32 * 72 * 2 + 34816 + 2048;    // 51,712
    cudaFuncSetAttribute(gemm_all,  cudaFuncAttributeMaxDynamicSharedMemorySize, smem_gemm);
    cudaFuncSetAttribute(gemm_proj, cudaFuncAttributeMaxDynamicSharedMemorySize, smem_gemm);
    cudaFuncSetAttribute(dwconv_wsplit, cudaFuncAttributeMaxDynamicSharedMemorySize, smem_dw);
    cudaFuncSetAttribute(attn_b1, cudaFuncAttributeMaxDynamicSharedMemorySize, smem_a1);
    cudaFuncSetAttribute(attn_b2, cudaFuncAttributeMaxDynamicSharedMemorySize, smem_a2);

    // 0: dwconv (+x fp16) + weight split
    dwconv_wsplit<<<768, 512, smem_dw>>>(
        x, p_xh, sr1_w, sr1_b, ln1_g, ln1_b, sr2_w, sr2_b, ln2_g, ln2_b,
        p_x1p, p_x2p,
        q_w, kv1_w, kv2_w, proj_w,
        p_qwf, p_k1wh, p_k1wl, p_k2wh, p_k2wl, p_pwh, p_pwl);
    // 1: all projections (q 256 [fp16 1-term] + kv1 16 + kv2 4 blocks)
    gemm_all<<<276, 512, smem_gemm>>>(
        p_xh, p_x1p, p_x2p, p_qwf,
        p_k1wh, p_k1wl, p_k2wh, p_k2wl,
        p_qh, p_kv1, p_k1h, p_kv2, p_k2h);
    // 2: v local conv -> V^T fp16 plane
    vconv_fused<<<BATCH * 256 + BATCH * 64, 128>>>(
        p_kv1, lc1_w, lc1_b, p_v1h,
        p_kv2, lc2_w, lc2_b, p_v2h);
    // 3: attention branch 1 (PROFILED SLOT)
    attn_b1<<<dim3(32, 64), 256, smem_a1>>>(p_qh, p_k1h, p_v1h, p_catp);
    // 4: attention branch 2
    attn_b2<<<dim3(32, 64), 256, smem_a2>>>(p_qh, p_k2h, p_v2h, p_catp);
    // 5: output projection
    gemm_proj<<<256, 512, smem_gemm>>>(p_catp, p_pwh, p_pwl, proj_b, out);
}